// round 1
// baseline (speedup 1.0000x reference)
#include <cuda_runtime.h>

// Problem constants (fixed shapes per reference: B=32768, D=512)
#define DD 512
#define BM 128
#define BN 128
#define BK 16
#define NSPLIT 32
#define MAXB 32768

typedef unsigned long long ull;

// ---------------- scratch (static device globals; no allocation) ----------------
__device__ float g_stim_out[(size_t)MAXB * DD];
__device__ float g_rec_out[(size_t)MAXB * DD];
__device__ float g_partS[(size_t)NSPLIT * DD * DD];
__device__ float g_partP[(size_t)NSPLIT * DD * DD];
__device__ float g_GS[DD * DD];
__device__ float g_GP[DD * DD];

// ---------------- packed f32x2 helpers ----------------
__device__ __forceinline__ ull dup2(float a) {
    ull r;
    asm("mov.b64 %0, {%1, %1};" : "=l"(r) : "f"(a));
    return r;
}
__device__ __forceinline__ void fma2(ull& c, ull a, ull b) {
    asm("fma.rn.f32x2 %0, %1, %2, %0;" : "+l"(c) : "l"(a), "l"(b));
}
__device__ __forceinline__ float2 unpack2(ull v) {
    float2 f;
    asm("mov.b64 {%0, %1}, %2;" : "=f"(f.x), "=f"(f.y) : "l"(v));
    return f;
}

// 8x8 microkernel over one BK-deep smem tile pair.
// acc[i][j] holds a packed pair of two adjacent output columns.
#define MICRO_KK(AsArr, BsArr)                                                  \
    do {                                                                        \
        _Pragma("unroll")                                                       \
        for (int kk = 0; kk < BK; ++kk) {                                       \
            float4 a0 = *(const float4*)&AsArr[kk][tr * 8];                     \
            float4 a1 = *(const float4*)&AsArr[kk][tr * 8 + 4];                 \
            ull ad[8] = {dup2(a0.x), dup2(a0.y), dup2(a0.z), dup2(a0.w),        \
                         dup2(a1.x), dup2(a1.y), dup2(a1.z), dup2(a1.w)};       \
            ulonglong2 bv0 = *(const ulonglong2*)&BsArr[kk][tc * 8];            \
            ulonglong2 bv1 = *(const ulonglong2*)&BsArr[kk][tc * 8 + 4];        \
            ull bq[4] = {bv0.x, bv0.y, bv1.x, bv1.y};                           \
            _Pragma("unroll")                                                   \
            for (int i = 0; i < 8; ++i) {                                       \
                _Pragma("unroll")                                               \
                for (int jj = 0; jj < 4; ++jj) fma2(acc[i][jj], ad[i], bq[jj]); \
            }                                                                   \
        }                                                                       \
    } while (0)

// ---------------- forward GEMM: O[M,512] = A[M,512] @ Bm[512,512] ----------------
__global__ __launch_bounds__(256) void sgemm_xw(const float* __restrict__ A,
                                                const float* __restrict__ Bm,
                                                float* __restrict__ O) {
    __shared__ __align__(16) float As[BK][BM + 4];  // transposed A tile (k-major), padded
    __shared__ __align__(16) float Bs[BK][BN];

    const int tid = threadIdx.x;
    const int m0 = blockIdx.y * BM;
    const int n0 = blockIdx.x * BN;
    const int tr = tid / 16;
    const int tc = tid % 16;

    ull acc[8][4];
#pragma unroll
    for (int i = 0; i < 8; ++i)
#pragma unroll
        for (int j = 0; j < 4; ++j) acc[i][j] = 0ull;

    const int arow = tid >> 2;          // 0..63
    const int acg = (tid & 3) * 4;      // 0,4,8,12
    const int brow = tid >> 5;          // 0..7
    const int bcg = (tid & 31) * 4;     // 0..124

    for (int k0 = 0; k0 < DD; k0 += BK) {
#pragma unroll
        for (int r = 0; r < 2; ++r) {
            int row = arow + r * 64;
            float4 v = *(const float4*)&A[(size_t)(m0 + row) * DD + k0 + acg];
            As[acg + 0][row] = v.x;
            As[acg + 1][row] = v.y;
            As[acg + 2][row] = v.z;
            As[acg + 3][row] = v.w;
        }
#pragma unroll
        for (int r = 0; r < 2; ++r) {
            int row = brow + r * 8;
            float4 v = *(const float4*)&Bm[(size_t)(k0 + row) * DD + n0 + bcg];
            *(float4*)&Bs[row][bcg] = v;
        }
        __syncthreads();
        MICRO_KK(As, Bs);
        __syncthreads();
    }

#pragma unroll
    for (int i = 0; i < 8; ++i) {
        int gm = m0 + tr * 8 + i;
        float2 f0 = unpack2(acc[i][0]);
        float2 f1 = unpack2(acc[i][1]);
        float2 f2 = unpack2(acc[i][2]);
        float2 f3 = unpack2(acc[i][3]);
        float4 o0 = make_float4(f0.x, f0.y, f1.x, f1.y);
        float4 o1 = make_float4(f2.x, f2.y, f3.x, f3.y);
        *(float4*)&O[(size_t)gm * DD + n0 + tc * 8] = o0;
        *(float4*)&O[(size_t)gm * DD + n0 + tc * 8 + 4] = o1;
    }
}

// ---------------- Gram partial: part[z] = X[z-chunk]^T @ X[z-chunk] ----------------
__global__ __launch_bounds__(256) void gram_partial(const float* __restrict__ X,
                                                    float* __restrict__ part, int KC) {
    __shared__ __align__(16) float Xi[BK][BM];
    __shared__ __align__(16) float Xj[BK][BN];

    const int tid = threadIdx.x;
    const int i0 = blockIdx.y * BM;
    const int j0 = blockIdx.x * BN;
    const int b0 = blockIdx.z * KC;
    const int tr = tid / 16;
    const int tc = tid % 16;

    ull acc[8][4];
#pragma unroll
    for (int i = 0; i < 8; ++i)
#pragma unroll
        for (int j = 0; j < 4; ++j) acc[i][j] = 0ull;

    const int lrow = tid >> 5;        // 0..7
    const int lcg = (tid & 31) * 4;   // 0..124

    for (int kt = 0; kt < KC; kt += BK) {
#pragma unroll
        for (int r = 0; r < 2; ++r) {
            int row = lrow + 8 * r;
            size_t base = (size_t)(b0 + kt + row) * DD;
            float4 vi = *(const float4*)&X[base + i0 + lcg];
            *(float4*)&Xi[row][lcg] = vi;
            float4 vj = *(const float4*)&X[base + j0 + lcg];
            *(float4*)&Xj[row][lcg] = vj;
        }
        __syncthreads();
        MICRO_KK(Xi, Xj);
        __syncthreads();
    }

    float* pout = part + (size_t)blockIdx.z * DD * DD;
#pragma unroll
    for (int i = 0; i < 8; ++i) {
        int gi = i0 + tr * 8 + i;
        float2 f0 = unpack2(acc[i][0]);
        float2 f1 = unpack2(acc[i][1]);
        float2 f2 = unpack2(acc[i][2]);
        float2 f3 = unpack2(acc[i][3]);
        float4 o0 = make_float4(f0.x, f0.y, f1.x, f1.y);
        float4 o1 = make_float4(f2.x, f2.y, f3.x, f3.y);
        *(float4*)&pout[(size_t)gi * DD + j0 + tc * 8] = o0;
        *(float4*)&pout[(size_t)gi * DD + j0 + tc * 8 + 4] = o1;
    }
}

// ---------------- reduce split-K Gram partials (deterministic order) ----------------
__global__ void reduce_gram() {
    int idx = blockIdx.x * blockDim.x + threadIdx.x;  // 262144 threads
    float s = 0.f, p = 0.f;
#pragma unroll 8
    for (int z = 0; z < NSPLIT; ++z) {
        s += g_partS[(size_t)z * DD * DD + idx];
        p += g_partP[(size_t)z * DD * DD + idx];
    }
    g_GS[idx] = s;
    g_GP[idx] = p;
}

// ---------------- fused LN(rec) -> add stim -> relu -> LN(act) ----------------
__global__ __launch_bounds__(512) void ln_fuse(const float* __restrict__ rec,
                                               const float* __restrict__ stim,
                                               const float* __restrict__ grec,
                                               const float* __restrict__ brec,
                                               const float* __restrict__ gact,
                                               const float* __restrict__ bact,
                                               float* __restrict__ out) {
    const int row = blockIdx.x;
    const int t = threadIdx.x;
    const int lane = t & 31;
    const int w = t >> 5;
    __shared__ float r1[32], r2[32];
    __shared__ float s1[32], s2[32];

    float x = rec[(size_t)row * DD + t];
    float a = x, b = x * x;
#pragma unroll
    for (int o = 16; o; o >>= 1) {
        a += __shfl_xor_sync(0xffffffffu, a, o);
        b += __shfl_xor_sync(0xffffffffu, b, o);
    }
    if (lane == 0) { r1[w] = a; r2[w] = b; }
    __syncthreads();
    if (w == 0) {
        a = (lane < 16) ? r1[lane] : 0.f;
        b = (lane < 16) ? r2[lane] : 0.f;
#pragma unroll
        for (int o = 16; o; o >>= 1) {
            a += __shfl_xor_sync(0xffffffffu, a, o);
            b += __shfl_xor_sync(0xffffffffu, b, o);
        }
        if (lane == 0) { r1[0] = a; r2[0] = b; }
    }
    __syncthreads();
    float mu = r1[0] * (1.f / DD);
    float var = r2[0] * (1.f / DD) - mu * mu;
    float rn = (x - mu) * rsqrtf(var + 1e-5f) * grec[t] + brec[t];

    float v = fmaxf(stim[(size_t)row * DD + t] + rn, 0.f);
    a = v;
    b = v * v;
#pragma unroll
    for (int o = 16; o; o >>= 1) {
        a += __shfl_xor_sync(0xffffffffu, a, o);
        b += __shfl_xor_sync(0xffffffffu, b, o);
    }
    if (lane == 0) { s1[w] = a; s2[w] = b; }
    __syncthreads();
    if (w == 0) {
        a = (lane < 16) ? s1[lane] : 0.f;
        b = (lane < 16) ? s2[lane] : 0.f;
#pragma unroll
        for (int o = 16; o; o >>= 1) {
            a += __shfl_xor_sync(0xffffffffu, a, o);
            b += __shfl_xor_sync(0xffffffffu, b, o);
        }
        if (lane == 0) { s1[0] = a; s2[0] = b; }
    }
    __syncthreads();
    float mu2 = s1[0] * (1.f / DD);
    float var2 = s2[0] * (1.f / DD) - mu2 * mu2;
    out[(size_t)row * DD + t] = (v - mu2) * rsqrtf(var2 + 1e-5f) * gact[t] + bact[t];
}

// ---------- weight update: out = l2norm_rows(W*(1-decay_i) + alpha_j*(G@W)) ----------
#define RPC 8
__global__ __launch_bounds__(512) void weight_update(const float* __restrict__ Wm,
                                                     const float* __restrict__ G,
                                                     const float* __restrict__ alpha,
                                                     const float* __restrict__ decay,
                                                     float* __restrict__ out) {
    const int i0 = blockIdx.x * RPC;
    const int j = threadIdx.x;
    const int lane = j & 31;
    const int w = j >> 5;

    __shared__ float Gsm[RPC][DD];
    __shared__ float red[16];
    __shared__ float norms[RPC];

#pragma unroll
    for (int r = 0; r < RPC; ++r) Gsm[r][j] = G[(size_t)(i0 + r) * DD + j];
    __syncthreads();

    float acc[RPC];
#pragma unroll
    for (int r = 0; r < RPC; ++r) acc[r] = 0.f;

#pragma unroll 4
    for (int k = 0; k < DD; ++k) {
        float wv = Wm[(size_t)k * DD + j];
#pragma unroll
        for (int r = 0; r < RPC; ++r) acc[r] = fmaf(Gsm[r][k], wv, acc[r]);
    }

    float aj = alpha[j];
#pragma unroll
    for (int r = 0; r < RPC; ++r) {
        float m = Wm[(size_t)(i0 + r) * DD + j] * (1.f - decay[i0 + r]) + aj * acc[r];
        acc[r] = m;
    }

    for (int r = 0; r < RPC; ++r) {
        float s = acc[r] * acc[r];
#pragma unroll
        for (int o = 16; o; o >>= 1) s += __shfl_xor_sync(0xffffffffu, s, o);
        if (lane == 0) red[w] = s;
        __syncthreads();
        if (j == 0) {
            float tsum = 0.f;
#pragma unroll
            for (int q = 0; q < 16; ++q) tsum += red[q];
            norms[r] = fmaxf(sqrtf(tsum), 1e-12f);
        }
        __syncthreads();
    }

#pragma unroll
    for (int r = 0; r < RPC; ++r)
        out[(size_t)(i0 + r) * DD + j] = acc[r] / norms[r];
}

// ---------------- launch ----------------
extern "C" void kernel_launch(void* const* d_in, const int* in_sizes, int n_in,
                              void* d_out, int out_size) {
    const float* stim = (const float*)d_in[0];
    const float* prev = (const float*)d_in[1];
    const float* W    = (const float*)d_in[2];
    const float* Wr   = (const float*)d_in[3];
    const float* alpha = (const float*)d_in[4];
    const float* decay = (const float*)d_in[5];
    const float* gact = (const float*)d_in[6];
    const float* bact = (const float*)d_in[7];
    const float* grec = (const float*)d_in[8];
    const float* brec = (const float*)d_in[9];
    float* out = (float*)d_out;

    const int Brows = in_sizes[0] / DD;  // 32768

    float *stim_out, *rec_out, *partS, *partP, *GS, *GP;
    cudaGetSymbolAddress((void**)&stim_out, g_stim_out);
    cudaGetSymbolAddress((void**)&rec_out, g_rec_out);
    cudaGetSymbolAddress((void**)&partS, g_partS);
    cudaGetSymbolAddress((void**)&partP, g_partP);
    cudaGetSymbolAddress((void**)&GS, g_GS);
    cudaGetSymbolAddress((void**)&GP, g_GP);

    dim3 gF(DD / BN, Brows / BM);                 // (4, 256)
    sgemm_xw<<<gF, 256>>>(stim, W, stim_out);
    sgemm_xw<<<gF, 256>>>(prev, Wr, rec_out);

    dim3 gG(DD / BN, DD / BM, NSPLIT);            // (4, 4, 32)
    const int KC = Brows / NSPLIT;                // 1024
    gram_partial<<<gG, 256>>>(stim, partS, KC);
    gram_partial<<<gG, 256>>>(prev, partP, KC);

    reduce_gram<<<(DD * DD) / 256, 256>>>();

    ln_fuse<<<Brows, 512>>>(rec_out, stim_out, grec, brec, gact, bact, out);

    size_t off = (size_t)Brows * DD;
    weight_update<<<DD / RPC, 512>>>(W, GS, alpha, decay, out + off);
    weight_update<<<DD / RPC, 512>>>(Wr, GP, alpha, decay, out + off + (size_t)DD * DD);
}

// round 3
// speedup vs baseline: 1.8894x; 1.8894x over previous
#include <cuda_runtime.h>
#include <cuda_bf16.h>
#include <cstdint>

typedef __nv_bfloat16 bf16;

// ---------------- problem constants ----------------
#define DD 512
#define MAXB 32768
#define NSPLIT 32
#define BKT 64                         // K per stage (bf16 elems) -> 128B rows
#define MT 128
#define NT 128
#define TILE_B (MT * BKT * 2)          // 16384 bytes per operand tile
#define STAGE_B (4 * TILE_B)           // 65536 (Ahi, Alo, Bhi, Blo)
#define NSTAGE 3
#define SMEM_DYN (NSTAGE * STAGE_B + 128)

// ---------------- scratch (device globals; no allocation) ----------------
__device__ __align__(256) bf16 g_s_hi[(size_t)MAXB * DD];
__device__ __align__(256) bf16 g_s_lo[(size_t)MAXB * DD];
__device__ __align__(256) bf16 g_p_hi[(size_t)MAXB * DD];
__device__ __align__(256) bf16 g_p_lo[(size_t)MAXB * DD];
__device__ __align__(256) bf16 g_st_hi[(size_t)DD * MAXB];
__device__ __align__(256) bf16 g_st_lo[(size_t)DD * MAXB];
__device__ __align__(256) bf16 g_pt_hi[(size_t)DD * MAXB];
__device__ __align__(256) bf16 g_pt_lo[(size_t)DD * MAXB];
__device__ __align__(256) bf16 g_wt_hi[DD * DD];
__device__ __align__(256) bf16 g_wt_lo[DD * DD];
__device__ __align__(256) bf16 g_wrt_hi[DD * DD];
__device__ __align__(256) bf16 g_wrt_lo[DD * DD];
__device__ __align__(256) float g_stim_out[(size_t)MAXB * DD];
__device__ __align__(256) float g_rec_out[(size_t)MAXB * DD];
__device__ __align__(256) float g_partS[(size_t)NSPLIT * DD * DD];
__device__ __align__(256) float g_partP[(size_t)NSPLIT * DD * DD];
__device__ __align__(256) float g_GS[DD * DD];
__device__ __align__(256) float g_GP[DD * DD];

// ---------------- PTX helpers (base-ISA only: sm_80+ safe) ----------------
__device__ __forceinline__ uint32_t smem_u32(const void* p) {
    uint32_t a;
    asm("{ .reg .u64 t; cvta.to.shared.u64 t, %1; cvt.u32.u64 %0, t; }" : "=r"(a) : "l"(p));
    return a;
}
__device__ __forceinline__ void ldsm_x4(uint32_t* r, uint32_t addr) {
    asm volatile("ldmatrix.sync.aligned.m8n8.x4.shared.b16 {%0,%1,%2,%3}, [%4];"
                 : "=r"(r[0]), "=r"(r[1]), "=r"(r[2]), "=r"(r[3]) : "r"(addr));
}
__device__ __forceinline__ void mma16816(float* c, const uint32_t* a, uint32_t b0, uint32_t b1) {
    asm volatile(
        "mma.sync.aligned.m16n8k16.row.col.f32.bf16.bf16.f32 "
        "{%0,%1,%2,%3}, {%4,%5,%6,%7}, {%8,%9}, {%0,%1,%2,%3};"
        : "+f"(c[0]), "+f"(c[1]), "+f"(c[2]), "+f"(c[3])
        : "r"(a[0]), "r"(a[1]), "r"(a[2]), "r"(a[3]), "r"(b0), "r"(b1));
}
__device__ __forceinline__ void cp16(uint32_t dst, const void* src) {
    asm volatile("cp.async.cg.shared.global [%0], [%1], 16;" :: "r"(dst), "l"(src) : "memory");
}
#define CP_COMMIT() asm volatile("cp.async.commit_group;" ::: "memory")

// swizzled smem byte offset within a tile: 128B rows, 8 x 16B chunks, chunk xor (row&7)
__device__ __forceinline__ uint32_t swz(int row, int chunk) {
    return (uint32_t)(row * 128 + ((chunk ^ (row & 7)) << 4));
}

// ---------------- stage loader: 4 tiles (Ahi, Alo, Bhi, Blo), cp.async ----------------
__device__ __forceinline__ void load_stage(uint32_t sb,
                                           const bf16* __restrict__ Ahi, const bf16* __restrict__ Alo,
                                           const bf16* __restrict__ Bhi, const bf16* __restrict__ Blo,
                                           long lda, long ldb, long m0, long n0, long k0, int tid) {
    const bf16* p0 = Ahi + m0 * lda + k0;
    const bf16* p1 = Alo + m0 * lda + k0;
    const bf16* p2 = Bhi + n0 * ldb + k0;
    const bf16* p3 = Blo + n0 * ldb + k0;
    const bf16* ptrs[4] = {p0, p1, p2, p3};
#pragma unroll
    for (int t = 0; t < 4; ++t) {
        long ld = (t < 2) ? lda : ldb;
        uint32_t tb = sb + t * TILE_B;
#pragma unroll
        for (int q = 0; q < 4; ++q) {
            int ci = tid + q * 256;       // 0..1023 chunk index (128 rows x 8 chunks)
            int row = ci >> 3, c = ci & 7;
            cp16(tb + swz(row, c), ptrs[t] + (long)row * ld + c * 8);
        }
    }
    CP_COMMIT();
}

// ---------------- mma.sync GEMM: C[M,N] = sum_k A[m,k]*B[n,k], bf16x3 ----------------
// gram!=0: blockIdx.x indexes upper-triangular 128-block pairs; blockIdx.z = split-K chunk.
__global__ __launch_bounds__(256, 1)
void mma_gemm(const bf16* __restrict__ Ahi, const bf16* __restrict__ Alo,
              const bf16* __restrict__ Bhi, const bf16* __restrict__ Blo,
              long lda, long ldb, int kc, float* __restrict__ C, int ldc,
              long pstride, int gram) {
    extern __shared__ char smraw[];
    const uint32_t base = (smem_u32(smraw) + 127u) & ~127u;

    const int tid = threadIdx.x;
    const int lane = tid & 31;
    const int wid = tid >> 5;
    const int wm = wid & 1;        // 2 warp-rows of 64
    const int wn = wid >> 1;       // 4 warp-cols of 32
    const int r15 = lane & 15;
    const int hi4 = lane >> 4;

    long m0, n0;
    if (gram) {
        const int PI[10] = {0, 0, 0, 0, 1, 1, 1, 2, 2, 3};
        const int PJ[10] = {0, 1, 2, 3, 1, 2, 3, 2, 3, 3};
        m0 = (long)PI[blockIdx.x] * MT;
        n0 = (long)PJ[blockIdx.x] * NT;
    } else {
        m0 = (long)blockIdx.y * MT;
        n0 = (long)blockIdx.x * NT;
    }
    const long kbase = (long)blockIdx.z * kc;
    const int niter = kc / BKT;
    C += (long)blockIdx.z * pstride;

    float acc[4][4][4];
#pragma unroll
    for (int i = 0; i < 4; ++i)
#pragma unroll
        for (int j = 0; j < 4; ++j)
#pragma unroll
            for (int q = 0; q < 4; ++q) acc[i][j][q] = 0.f;

    // prologue: fill NSTAGE-1 stages
    load_stage(base, Ahi, Alo, Bhi, Blo, lda, ldb, m0, n0, kbase, tid);
    load_stage(base + STAGE_B, Ahi, Alo, Bhi, Blo, lda, ldb, m0, n0, kbase + BKT, tid);

    for (int i = 0; i < niter; ++i) {
        if (i + 1 < niter) asm volatile("cp.async.wait_group 1;" ::: "memory");
        else               asm volatile("cp.async.wait_group 0;" ::: "memory");
        __syncthreads();

        if (i + 2 < niter)
            load_stage(base + ((i + 2) % NSTAGE) * STAGE_B, Ahi, Alo, Bhi, Blo,
                       lda, ldb, m0, n0, kbase + (long)(i + 2) * BKT, tid);

        const uint32_t sb = base + (i % NSTAGE) * STAGE_B;
        const uint32_t Ah = sb, Al = sb + TILE_B, Bh = sb + 2 * TILE_B, Bl = sb + 3 * TILE_B;

#pragma unroll
        for (int ks = 0; ks < 4; ++ks) {
            uint32_t ah[4][4], al[4][4], bh[2][4], bl[2][4];
#pragma unroll
            for (int mt = 0; mt < 4; ++mt) {
                int row = wm * 64 + mt * 16 + r15;
                int ck = 2 * ks + hi4;
                ldsm_x4(ah[mt], Ah + swz(row, ck));
                ldsm_x4(al[mt], Al + swz(row, ck));
            }
#pragma unroll
            for (int np = 0; np < 2; ++np) {
                int row = wn * 32 + np * 16 + r15;
                int ck = 2 * ks + hi4;
                ldsm_x4(bh[np], Bh + swz(row, ck));
                ldsm_x4(bl[np], Bl + swz(row, ck));
            }
#pragma unroll
            for (int mt = 0; mt < 4; ++mt)
#pragma unroll
                for (int nt = 0; nt < 4; ++nt) {
                    int np = nt >> 1, p = nt & 1;
                    mma16816(acc[mt][nt], ah[mt], bh[np][p], bh[np][p + 2]);
                    mma16816(acc[mt][nt], ah[mt], bl[np][p], bl[np][p + 2]);
                    mma16816(acc[mt][nt], al[mt], bh[np][p], bh[np][p + 2]);
                }
        }
    }

    // epilogue: write fp32 directly from accumulators
#pragma unroll
    for (int mt = 0; mt < 4; ++mt) {
        long row = m0 + wm * 64 + mt * 16 + (lane >> 2);
#pragma unroll
        for (int nt = 0; nt < 4; ++nt) {
            long col = n0 + wn * 32 + nt * 8 + 2 * (lane & 3);
            *(float2*)&C[row * ldc + col] = make_float2(acc[mt][nt][0], acc[mt][nt][1]);
            *(float2*)&C[(row + 8) * ldc + col] = make_float2(acc[mt][nt][2], acc[mt][nt][3]);
        }
    }
}

// ---------------- prep: fp32 -> (hi, lo) bf16, row-major ----------------
__global__ __launch_bounds__(256) void split_rm(const float4* __restrict__ X,
                                                uint4* __restrict__ Hi, uint4* __restrict__ Lo) {
    long i = (long)blockIdx.x * blockDim.x + threadIdx.x;
    float4 a = X[2 * i], b = X[2 * i + 1];
    float v[8] = {a.x, a.y, a.z, a.w, b.x, b.y, b.z, b.w};
    unsigned short h[8], l[8];
#pragma unroll
    for (int e = 0; e < 8; ++e) {
        bf16 hb = __float2bfloat16(v[e]);
        h[e] = __bfloat16_as_ushort(hb);
        l[e] = __bfloat16_as_ushort(__float2bfloat16(v[e] - __bfloat162float(hb)));
    }
    Hi[i] = make_uint4(h[0] | (uint32_t)h[1] << 16, h[2] | (uint32_t)h[3] << 16,
                       h[4] | (uint32_t)h[5] << 16, h[6] | (uint32_t)h[7] << 16);
    Lo[i] = make_uint4(l[0] | (uint32_t)l[1] << 16, l[2] | (uint32_t)l[3] << 16,
                       l[4] | (uint32_t)l[5] << 16, l[6] | (uint32_t)l[7] << 16);
}

// ---------------- prep: fp32 X[R,C] -> transposed (hi, lo) bf16 T[C,R] ----------------
__global__ __launch_bounds__(256) void split_tr(const float* __restrict__ X,
                                                bf16* __restrict__ Th, bf16* __restrict__ Tl,
                                                long R, long C) {
    __shared__ float s[32][33];
    const int tx = threadIdx.x, ty = threadIdx.y;
    const long c0 = (long)blockIdx.x * 32, r0 = (long)blockIdx.y * 32;
#pragma unroll
    for (int i = 0; i < 4; ++i)
        s[tx][ty + 8 * i] = X[(r0 + ty + 8 * i) * C + c0 + tx];
    __syncthreads();
#pragma unroll
    for (int i = 0; i < 4; ++i) {
        float v = s[ty + 8 * i][tx];
        bf16 hb = __float2bfloat16(v);
        long o = (c0 + ty + 8 * i) * R + r0 + tx;
        Th[o] = hb;
        Tl[o] = __float2bfloat16(v - __bfloat162float(hb));
    }
}

// ---------------- reduce split-K Gram partials (symmetric mirror) ----------------
__global__ void reduce_gram() {
    int idx = blockIdx.x * blockDim.x + threadIdx.x;
    int i = idx >> 9, j = idx & 511;
    size_t src = ((i >> 7) <= (j >> 7)) ? ((size_t)i * DD + j) : ((size_t)j * DD + i);
    float s = 0.f, p = 0.f;
#pragma unroll 8
    for (int z = 0; z < NSPLIT; ++z) {
        s += g_partS[(size_t)z * DD * DD + src];
        p += g_partP[(size_t)z * DD * DD + src];
    }
    g_GS[idx] = s;
    g_GP[idx] = p;
}

// ---------------- fused LN(rec) -> add stim -> relu -> LN(act) ----------------
__global__ __launch_bounds__(512) void ln_fuse(const float* __restrict__ rec,
                                               const float* __restrict__ stim,
                                               const float* __restrict__ grec,
                                               const float* __restrict__ brec,
                                               const float* __restrict__ gact,
                                               const float* __restrict__ bact,
                                               float* __restrict__ out) {
    const int row = blockIdx.x;
    const int t = threadIdx.x;
    const int lane = t & 31;
    const int w = t >> 5;
    __shared__ float r1[32], r2[32], s1[32], s2[32];

    float x = rec[(size_t)row * DD + t];
    float a = x, b = x * x;
#pragma unroll
    for (int o = 16; o; o >>= 1) {
        a += __shfl_xor_sync(0xffffffffu, a, o);
        b += __shfl_xor_sync(0xffffffffu, b, o);
    }
    if (lane == 0) { r1[w] = a; r2[w] = b; }
    __syncthreads();
    if (w == 0) {
        a = (lane < 16) ? r1[lane] : 0.f;
        b = (lane < 16) ? r2[lane] : 0.f;
#pragma unroll
        for (int o = 16; o; o >>= 1) {
            a += __shfl_xor_sync(0xffffffffu, a, o);
            b += __shfl_xor_sync(0xffffffffu, b, o);
        }
        if (lane == 0) { r1[0] = a; r2[0] = b; }
    }
    __syncthreads();
    float mu = r1[0] * (1.f / DD);
    float var = r2[0] * (1.f / DD) - mu * mu;
    float rn = (x - mu) * rsqrtf(var + 1e-5f) * grec[t] + brec[t];

    float v = fmaxf(stim[(size_t)row * DD + t] + rn, 0.f);
    a = v;
    b = v * v;
#pragma unroll
    for (int o = 16; o; o >>= 1) {
        a += __shfl_xor_sync(0xffffffffu, a, o);
        b += __shfl_xor_sync(0xffffffffu, b, o);
    }
    if (lane == 0) { s1[w] = a; s2[w] = b; }
    __syncthreads();
    if (w == 0) {
        a = (lane < 16) ? s1[lane] : 0.f;
        b = (lane < 16) ? s2[lane] : 0.f;
#pragma unroll
        for (int o = 16; o; o >>= 1) {
            a += __shfl_xor_sync(0xffffffffu, a, o);
            b += __shfl_xor_sync(0xffffffffu, b, o);
        }
        if (lane == 0) { s1[0] = a; s2[0] = b; }
    }
    __syncthreads();
    float mu2 = s1[0] * (1.f / DD);
    float var2 = s2[0] * (1.f / DD) - mu2 * mu2;
    out[(size_t)row * DD + t] = (v - mu2) * rsqrtf(var2 + 1e-5f) * gact[t] + bact[t];
}

// ---------- weight update: out = l2norm_rows(W*(1-decay_i) + alpha_j*(G@W)) ----------
#define RPC 8
__global__ __launch_bounds__(512) void weight_update(const float* __restrict__ Wm,
                                                     const float* __restrict__ G,
                                                     const float* __restrict__ alpha,
                                                     const float* __restrict__ decay,
                                                     float* __restrict__ out) {
    const int i0 = blockIdx.x * RPC;
    const int j = threadIdx.x;
    const int lane = j & 31;
    const int w = j >> 5;

    __shared__ float Gsm[RPC][DD];
    __shared__ float red[16];
    __shared__ float norms[RPC];

#pragma unroll
    for (int r = 0; r < RPC; ++r) Gsm[r][j] = G[(size_t)(i0 + r) * DD + j];
    __syncthreads();

    float acc[RPC];
#pragma unroll
    for (int r = 0; r < RPC; ++r) acc[r] = 0.f;

#pragma unroll 4
    for (int k = 0; k < DD; ++k) {
        float wv = Wm[(size_t)k * DD + j];
#pragma unroll
        for (int r = 0; r < RPC; ++r) acc[r] = fmaf(Gsm[r][k], wv, acc[r]);
    }

    float aj = alpha[j];
#pragma unroll
    for (int r = 0; r < RPC; ++r)
        acc[r] = Wm[(size_t)(i0 + r) * DD + j] * (1.f - decay[i0 + r]) + aj * acc[r];

    for (int r = 0; r < RPC; ++r) {
        float s = acc[r] * acc[r];
#pragma unroll
        for (int o = 16; o; o >>= 1) s += __shfl_xor_sync(0xffffffffu, s, o);
        if (lane == 0) red[w] = s;
        __syncthreads();
        if (j == 0) {
            float tsum = 0.f;
#pragma unroll
            for (int q = 0; q < 16; ++q) tsum += red[q];
            norms[r] = fmaxf(sqrtf(tsum), 1e-12f);
        }
        __syncthreads();
    }

#pragma unroll
    for (int r = 0; r < RPC; ++r)
        out[(size_t)(i0 + r) * DD + j] = acc[r] / norms[r];
}

// ---------------- launch ----------------
extern "C" void kernel_launch(void* const* d_in, const int* in_sizes, int n_in,
                              void* d_out, int out_size) {
    const float* stim = (const float*)d_in[0];
    const float* prev = (const float*)d_in[1];
    const float* W    = (const float*)d_in[2];
    const float* Wr   = (const float*)d_in[3];
    const float* alpha = (const float*)d_in[4];
    const float* decay = (const float*)d_in[5];
    const float* gact = (const float*)d_in[6];
    const float* bact = (const float*)d_in[7];
    const float* grec = (const float*)d_in[8];
    const float* brec = (const float*)d_in[9];
    float* out = (float*)d_out;

    const long Brows = in_sizes[0] / DD;  // 32768

    bf16 *s_hi, *s_lo, *p_hi, *p_lo, *st_hi, *st_lo, *pt_hi, *pt_lo;
    bf16 *wt_hi, *wt_lo, *wrt_hi, *wrt_lo;
    float *stim_out, *rec_out, *partS, *partP, *GS, *GP;
    cudaGetSymbolAddress((void**)&s_hi, g_s_hi);
    cudaGetSymbolAddress((void**)&s_lo, g_s_lo);
    cudaGetSymbolAddress((void**)&p_hi, g_p_hi);
    cudaGetSymbolAddress((void**)&p_lo, g_p_lo);
    cudaGetSymbolAddress((void**)&st_hi, g_st_hi);
    cudaGetSymbolAddress((void**)&st_lo, g_st_lo);
    cudaGetSymbolAddress((void**)&pt_hi, g_pt_hi);
    cudaGetSymbolAddress((void**)&pt_lo, g_pt_lo);
    cudaGetSymbolAddress((void**)&wt_hi, g_wt_hi);
    cudaGetSymbolAddress((void**)&wt_lo, g_wt_lo);
    cudaGetSymbolAddress((void**)&wrt_hi, g_wrt_hi);
    cudaGetSymbolAddress((void**)&wrt_lo, g_wrt_lo);
    cudaGetSymbolAddress((void**)&stim_out, g_stim_out);
    cudaGetSymbolAddress((void**)&rec_out, g_rec_out);
    cudaGetSymbolAddress((void**)&partS, g_partS);
    cudaGetSymbolAddress((void**)&partP, g_partP);
    cudaGetSymbolAddress((void**)&GS, g_GS);
    cudaGetSymbolAddress((void**)&GP, g_GP);

    cudaFuncSetAttribute(mma_gemm, cudaFuncAttributeMaxDynamicSharedMemorySize, SMEM_DYN);

    // prep: row-major splits (forward A operands)
    long nvec = Brows * DD / 8;
    split_rm<<<nvec / 256, 256>>>((const float4*)stim, (uint4*)s_hi, (uint4*)s_lo);
    split_rm<<<nvec / 256, 256>>>((const float4*)prev, (uint4*)p_hi, (uint4*)p_lo);
    // prep: transposed splits (gram operands + weight B operands)
    dim3 tb(32, 8);
    split_tr<<<dim3(DD / 32, Brows / 32), tb>>>(stim, st_hi, st_lo, Brows, DD);
    split_tr<<<dim3(DD / 32, Brows / 32), tb>>>(prev, pt_hi, pt_lo, Brows, DD);
    split_tr<<<dim3(DD / 32, DD / 32), tb>>>(W, wt_hi, wt_lo, DD, DD);
    split_tr<<<dim3(DD / 32, DD / 32), tb>>>(Wr, wrt_hi, wrt_lo, DD, DD);

    // forward GEMMs: O[B,512] = X @ Wm (B operand = Wm^T, k-contiguous)
    dim3 gF(DD / NT, Brows / MT, 1);
    mma_gemm<<<gF, 256, SMEM_DYN>>>(s_hi, s_lo, wt_hi, wt_lo, DD, DD, DD, stim_out, DD, 0, 0);
    mma_gemm<<<gF, 256, SMEM_DYN>>>(p_hi, p_lo, wrt_hi, wrt_lo, DD, DD, DD, rec_out, DD, 0, 0);

    // gram GEMMs (split-K over batch, upper-triangular 128-blocks only)
    dim3 gG(10, 1, NSPLIT);
    int kc = (int)(Brows / NSPLIT);  // 1024
    mma_gemm<<<gG, 256, SMEM_DYN>>>(st_hi, st_lo, st_hi, st_lo, Brows, Brows, kc, partS, DD, (long)DD * DD, 1);
    mma_gemm<<<gG, 256, SMEM_DYN>>>(pt_hi, pt_lo, pt_hi, pt_lo, Brows, Brows, kc, partP, DD, (long)DD * DD, 1);

    reduce_gram<<<(DD * DD) / 256, 256>>>();

    ln_fuse<<<(unsigned)Brows, 512>>>(rec_out, stim_out, grec, brec, gact, bact, out);

    size_t off = (size_t)Brows * DD;
    weight_update<<<DD / RPC, 512>>>(W, GS, alpha, decay, out + off);
    weight_update<<<DD / RPC, 512>>>(Wr, GP, alpha, decay, out + off + (size_t)DD * DD);
}

// round 4
// speedup vs baseline: 2.0634x; 1.0921x over previous
#include <cuda_runtime.h>
#include <cuda_bf16.h>
#include <cstdint>

typedef __nv_bfloat16 bf16;

// ---------------- problem constants ----------------
#define DD 512
#define MAXB 32768
#define NSPLIT 32
#define BKT 64                         // K per stage (bf16 elems) -> 128B rows
#define MT 128
#define NT 128
#define TILE_B (MT * BKT * 2)          // 16384 bytes per operand tile
#define STAGE_B (4 * TILE_B)           // 65536 (Ahi, Alo, Bhi, Blo)
#define NSTAGE 3
#define SMEM_DYN (NSTAGE * STAGE_B + 128)

// ---------------- scratch (device globals; no allocation) ----------------
__device__ __align__(256) bf16 g_s_hi[(size_t)MAXB * DD];
__device__ __align__(256) bf16 g_s_lo[(size_t)MAXB * DD];
__device__ __align__(256) bf16 g_p_hi[(size_t)MAXB * DD];
__device__ __align__(256) bf16 g_p_lo[(size_t)MAXB * DD];
__device__ __align__(256) bf16 g_st_hi[(size_t)DD * MAXB];
__device__ __align__(256) bf16 g_st_lo[(size_t)DD * MAXB];
__device__ __align__(256) bf16 g_pt_hi[(size_t)DD * MAXB];
__device__ __align__(256) bf16 g_pt_lo[(size_t)DD * MAXB];
__device__ __align__(256) bf16 g_wt_hi[DD * DD];
__device__ __align__(256) bf16 g_wt_lo[DD * DD];
__device__ __align__(256) bf16 g_wrt_hi[DD * DD];
__device__ __align__(256) bf16 g_wrt_lo[DD * DD];
__device__ __align__(256) float g_stim_out[(size_t)MAXB * DD];
__device__ __align__(256) float g_rec_out[(size_t)MAXB * DD];
__device__ __align__(256) float g_partS[(size_t)NSPLIT * DD * DD];
__device__ __align__(256) float g_partP[(size_t)NSPLIT * DD * DD];
__device__ __align__(256) float g_GS[DD * DD];
__device__ __align__(256) float g_GP[DD * DD];

// ---------------- PTX helpers (base-ISA only: sm_80+ safe) ----------------
__device__ __forceinline__ uint32_t smem_u32(const void* p) {
    uint32_t a;
    asm("{ .reg .u64 t; cvta.to.shared.u64 t, %1; cvt.u32.u64 %0, t; }" : "=r"(a) : "l"(p));
    return a;
}
__device__ __forceinline__ void ldsm_x4(uint32_t* r, uint32_t addr) {
    asm volatile("ldmatrix.sync.aligned.m8n8.x4.shared.b16 {%0,%1,%2,%3}, [%4];"
                 : "=r"(r[0]), "=r"(r[1]), "=r"(r[2]), "=r"(r[3]) : "r"(addr));
}
__device__ __forceinline__ void mma16816(float* c, const uint32_t* a, uint32_t b0, uint32_t b1) {
    asm volatile(
        "mma.sync.aligned.m16n8k16.row.col.f32.bf16.bf16.f32 "
        "{%0,%1,%2,%3}, {%4,%5,%6,%7}, {%8,%9}, {%0,%1,%2,%3};"
        : "+f"(c[0]), "+f"(c[1]), "+f"(c[2]), "+f"(c[3])
        : "r"(a[0]), "r"(a[1]), "r"(a[2]), "r"(a[3]), "r"(b0), "r"(b1));
}
__device__ __forceinline__ void cp16(uint32_t dst, const void* src) {
    asm volatile("cp.async.cg.shared.global [%0], [%1], 16;" :: "r"(dst), "l"(src) : "memory");
}
#define CP_COMMIT() asm volatile("cp.async.commit_group;" ::: "memory")

// swizzled smem byte offset within a tile: 128B rows, 8 x 16B chunks, chunk xor (row&7)
__device__ __forceinline__ uint32_t swz(int row, int chunk) {
    return (uint32_t)(row * 128 + ((chunk ^ (row & 7)) << 4));
}

// ---------------- segment descriptor for the merged GEMM launch ----------------
struct Seg {
    const bf16 *Ah, *Al, *Bh, *Bl;
    long lda, ldb;
    float* C;
    long pstride;
    int kc;     // K per block (split-K chunk for gram, full K for forward)
    int gram;   // 0: forward tiling, 1: upper-tri gram tiling
    int blk0;   // first global block id of this segment
};
struct Seg4 { Seg s[4]; };

// ---------------- stage loader: 4 tiles (Ahi, Alo, Bhi, Blo), cp.async ----------------
__device__ __forceinline__ void load_stage(uint32_t sb,
                                           const bf16* __restrict__ Ahi, const bf16* __restrict__ Alo,
                                           const bf16* __restrict__ Bhi, const bf16* __restrict__ Blo,
                                           long lda, long ldb, long m0, long n0, long k0, int tid) {
    const bf16* ptrs[4] = {Ahi + m0 * lda + k0, Alo + m0 * lda + k0,
                           Bhi + n0 * ldb + k0, Blo + n0 * ldb + k0};
#pragma unroll
    for (int t = 0; t < 4; ++t) {
        long ld = (t < 2) ? lda : ldb;
        uint32_t tb = sb + t * TILE_B;
#pragma unroll
        for (int q = 0; q < 4; ++q) {
            int ci = tid + q * 256;       // 0..1023 chunk index (128 rows x 8 chunks)
            int row = ci >> 3, c = ci & 7;
            cp16(tb + swz(row, c), ptrs[t] + (long)row * ld + c * 8);
        }
    }
    CP_COMMIT();
}

// ---------------- merged mma.sync GEMM: all 4 GEMMs in one launch ----------------
__global__ __launch_bounds__(256, 1)
void mma_all(Seg4 segs) {
    extern __shared__ char smraw[];
    const uint32_t base = (smem_u32(smraw) + 127u) & ~127u;

    const int bid = blockIdx.x;
    int si = (bid >= segs.s[2].blk0) ? ((bid >= segs.s[3].blk0) ? 3 : 2)
                                     : ((bid >= segs.s[1].blk0) ? 1 : 0);
    const Seg sg = segs.s[si];
    const int b = bid - sg.blk0;

    const int tid = threadIdx.x;
    const int lane = tid & 31;
    const int wid = tid >> 5;
    const int wm = wid & 1;        // 2 warp-rows of 64
    const int wn = wid >> 1;       // 4 warp-cols of 32
    const int r15 = lane & 15;
    const int hi4 = lane >> 4;

    long m0, n0, kbase;
    float* C = sg.C;
    if (sg.gram) {
        const int PI[10] = {0, 0, 0, 0, 1, 1, 1, 2, 2, 3};
        const int PJ[10] = {0, 1, 2, 3, 1, 2, 3, 2, 3, 3};
        int p = b % 10, z = b / 10;
        m0 = (long)PI[p] * MT;
        n0 = (long)PJ[p] * NT;
        kbase = (long)z * sg.kc;
        C += (long)z * sg.pstride;
    } else {
        m0 = (long)(b >> 2) * MT;
        n0 = (long)(b & 3) * NT;
        kbase = 0;
    }
    const int niter = sg.kc / BKT;

    float acc[4][4][4];
#pragma unroll
    for (int i = 0; i < 4; ++i)
#pragma unroll
        for (int j = 0; j < 4; ++j)
#pragma unroll
            for (int q = 0; q < 4; ++q) acc[i][j][q] = 0.f;

    // prologue: fill NSTAGE-1 stages
    load_stage(base, sg.Ah, sg.Al, sg.Bh, sg.Bl, sg.lda, sg.ldb, m0, n0, kbase, tid);
    load_stage(base + STAGE_B, sg.Ah, sg.Al, sg.Bh, sg.Bl, sg.lda, sg.ldb, m0, n0, kbase + BKT, tid);

    for (int i = 0; i < niter; ++i) {
        if (i + 1 < niter) asm volatile("cp.async.wait_group 1;" ::: "memory");
        else               asm volatile("cp.async.wait_group 0;" ::: "memory");
        __syncthreads();

        if (i + 2 < niter)
            load_stage(base + ((i + 2) % NSTAGE) * STAGE_B, sg.Ah, sg.Al, sg.Bh, sg.Bl,
                       sg.lda, sg.ldb, m0, n0, kbase + (long)(i + 2) * BKT, tid);

        const uint32_t sb = base + (i % NSTAGE) * STAGE_B;
        const uint32_t Ah = sb, Al = sb + TILE_B, Bh = sb + 2 * TILE_B, Bl = sb + 3 * TILE_B;

#pragma unroll
        for (int ks = 0; ks < 4; ++ks) {
            uint32_t ah[4][4], al[4][4], bh[2][4], bl[2][4];
#pragma unroll
            for (int mt = 0; mt < 4; ++mt) {
                int row = wm * 64 + mt * 16 + r15;
                int ck = 2 * ks + hi4;
                ldsm_x4(ah[mt], Ah + swz(row, ck));
                ldsm_x4(al[mt], Al + swz(row, ck));
            }
#pragma unroll
            for (int np = 0; np < 2; ++np) {
                int row = wn * 32 + np * 16 + r15;
                int ck = 2 * ks + hi4;
                ldsm_x4(bh[np], Bh + swz(row, ck));
                ldsm_x4(bl[np], Bl + swz(row, ck));
            }
#pragma unroll
            for (int mt = 0; mt < 4; ++mt)
#pragma unroll
                for (int nt = 0; nt < 4; ++nt) {
                    int np = nt >> 1, p = nt & 1;
                    mma16816(acc[mt][nt], ah[mt], bh[np][p], bh[np][p + 2]);
                    mma16816(acc[mt][nt], ah[mt], bl[np][p], bl[np][p + 2]);
                    mma16816(acc[mt][nt], al[mt], bh[np][p], bh[np][p + 2]);
                }
        }
    }

    // epilogue: write fp32 directly from accumulators
#pragma unroll
    for (int mt = 0; mt < 4; ++mt) {
        long row = m0 + wm * 64 + mt * 16 + (lane >> 2);
#pragma unroll
        for (int nt = 0; nt < 4; ++nt) {
            long col = n0 + wn * 32 + nt * 8 + 2 * (lane & 3);
            *(float2*)&C[row * DD + col] = make_float2(acc[mt][nt][0], acc[mt][nt][1]);
            *(float2*)&C[(row + 8) * DD + col] = make_float2(acc[mt][nt][2], acc[mt][nt][3]);
        }
    }
}

// ---------------- prep: fp32 -> (hi, lo) bf16, row-major ----------------
__global__ __launch_bounds__(256) void split_rm(const float4* __restrict__ X,
                                                uint4* __restrict__ Hi, uint4* __restrict__ Lo) {
    long i = (long)blockIdx.x * blockDim.x + threadIdx.x;
    float4 a = X[2 * i], b = X[2 * i + 1];
    float v[8] = {a.x, a.y, a.z, a.w, b.x, b.y, b.z, b.w};
    unsigned short h[8], l[8];
#pragma unroll
    for (int e = 0; e < 8; ++e) {
        bf16 hb = __float2bfloat16(v[e]);
        h[e] = __bfloat16_as_ushort(hb);
        l[e] = __bfloat16_as_ushort(__float2bfloat16(v[e] - __bfloat162float(hb)));
    }
    Hi[i] = make_uint4(h[0] | (uint32_t)h[1] << 16, h[2] | (uint32_t)h[3] << 16,
                       h[4] | (uint32_t)h[5] << 16, h[6] | (uint32_t)h[7] << 16);
    Lo[i] = make_uint4(l[0] | (uint32_t)l[1] << 16, l[2] | (uint32_t)l[3] << 16,
                       l[4] | (uint32_t)l[5] << 16, l[6] | (uint32_t)l[7] << 16);
}

// ---------------- prep: fp32 X[R,C] -> transposed (hi, lo) bf16 T[C,R] ----------------
__global__ __launch_bounds__(256) void split_tr(const float* __restrict__ X,
                                                bf16* __restrict__ Th, bf16* __restrict__ Tl,
                                                long R, long C) {
    __shared__ float s[32][33];
    const int tx = threadIdx.x, ty = threadIdx.y;
    const long c0 = (long)blockIdx.x * 32, r0 = (long)blockIdx.y * 32;
#pragma unroll
    for (int i = 0; i < 4; ++i)
        s[tx][ty + 8 * i] = X[(r0 + ty + 8 * i) * C + c0 + tx];
    __syncthreads();
#pragma unroll
    for (int i = 0; i < 4; ++i) {
        float v = s[ty + 8 * i][tx];
        bf16 hb = __float2bfloat16(v);
        long o = (c0 + ty + 8 * i) * R + r0 + tx;
        Th[o] = hb;
        Tl[o] = __float2bfloat16(v - __bfloat162float(hb));
    }
}

// ------- fused prep: row-major hi/lo AND transposed hi/lo from one read -------
__global__ __launch_bounds__(256) void split_both(const float* __restrict__ X,
                                                  bf16* __restrict__ Hr, bf16* __restrict__ Lr,
                                                  bf16* __restrict__ Th, bf16* __restrict__ Tl,
                                                  long R, long C) {
    __shared__ float s[32][33];
    const int tx = threadIdx.x, ty = threadIdx.y;
    const long c0 = (long)blockIdx.x * 32, r0 = (long)blockIdx.y * 32;
#pragma unroll
    for (int i = 0; i < 4; ++i) {
        long row = r0 + ty + 8 * i;
        float v = X[row * C + c0 + tx];
        s[tx][ty + 8 * i] = v;
        bf16 hb = __float2bfloat16(v);
        long o = row * C + c0 + tx;
        Hr[o] = hb;
        Lr[o] = __float2bfloat16(v - __bfloat162float(hb));
    }
    __syncthreads();
#pragma unroll
    for (int i = 0; i < 4; ++i) {
        float v = s[ty + 8 * i][tx];
        bf16 hb = __float2bfloat16(v);
        long o = (c0 + ty + 8 * i) * R + r0 + tx;
        Th[o] = hb;
        Tl[o] = __float2bfloat16(v - __bfloat162float(hb));
    }
}

// ---------------- reduce split-K Gram partials (symmetric mirror) ----------------
__global__ void reduce_gram() {
    int idx = blockIdx.x * blockDim.x + threadIdx.x;
    int i = idx >> 9, j = idx & 511;
    size_t src = ((i >> 7) <= (j >> 7)) ? ((size_t)i * DD + j) : ((size_t)j * DD + i);
    float s = 0.f, p = 0.f;
#pragma unroll 8
    for (int z = 0; z < NSPLIT; ++z) {
        s += g_partS[(size_t)z * DD * DD + src];
        p += g_partP[(size_t)z * DD * DD + src];
    }
    g_GS[idx] = s;
    g_GP[idx] = p;
}

// ---------------- fused LN(rec) -> add stim -> relu -> LN(act) ----------------
__global__ __launch_bounds__(512) void ln_fuse(const float* __restrict__ rec,
                                               const float* __restrict__ stim,
                                               const float* __restrict__ grec,
                                               const float* __restrict__ brec,
                                               const float* __restrict__ gact,
                                               const float* __restrict__ bact,
                                               float* __restrict__ out) {
    const int row = blockIdx.x;
    const int t = threadIdx.x;
    const int lane = t & 31;
    const int w = t >> 5;
    __shared__ float r1[32], r2[32], s1[32], s2[32];

    float x = rec[(size_t)row * DD + t];
    float a = x, b = x * x;
#pragma unroll
    for (int o = 16; o; o >>= 1) {
        a += __shfl_xor_sync(0xffffffffu, a, o);
        b += __shfl_xor_sync(0xffffffffu, b, o);
    }
    if (lane == 0) { r1[w] = a; r2[w] = b; }
    __syncthreads();
    if (w == 0) {
        a = (lane < 16) ? r1[lane] : 0.f;
        b = (lane < 16) ? r2[lane] : 0.f;
#pragma unroll
        for (int o = 16; o; o >>= 1) {
            a += __shfl_xor_sync(0xffffffffu, a, o);
            b += __shfl_xor_sync(0xffffffffu, b, o);
        }
        if (lane == 0) { r1[0] = a; r2[0] = b; }
    }
    __syncthreads();
    float mu = r1[0] * (1.f / DD);
    float var = r2[0] * (1.f / DD) - mu * mu;
    float rn = (x - mu) * rsqrtf(var + 1e-5f) * grec[t] + brec[t];

    float v = fmaxf(stim[(size_t)row * DD + t] + rn, 0.f);
    a = v;
    b = v * v;
#pragma unroll
    for (int o = 16; o; o >>= 1) {
        a += __shfl_xor_sync(0xffffffffu, a, o);
        b += __shfl_xor_sync(0xffffffffu, b, o);
    }
    if (lane == 0) { s1[w] = a; s2[w] = b; }
    __syncthreads();
    if (w == 0) {
        a = (lane < 16) ? s1[lane] : 0.f;
        b = (lane < 16) ? s2[lane] : 0.f;
#pragma unroll
        for (int o = 16; o; o >>= 1) {
            a += __shfl_xor_sync(0xffffffffu, a, o);
            b += __shfl_xor_sync(0xffffffffu, b, o);
        }
        if (lane == 0) { s1[0] = a; s2[0] = b; }
    }
    __syncthreads();
    float mu2 = s1[0] * (1.f / DD);
    float var2 = s2[0] * (1.f / DD) - mu2 * mu2;
    out[(size_t)row * DD + t] = (v - mu2) * rsqrtf(var2 + 1e-5f) * gact[t] + bact[t];
}

// ---------- weight update: out = l2norm_rows(W*(1-decay_i) + alpha_j*(G@W)) ----------
#define RPC 8
__global__ __launch_bounds__(512) void weight_update(const float* __restrict__ Wm,
                                                     const float* __restrict__ G,
                                                     const float* __restrict__ alpha,
                                                     const float* __restrict__ decay,
                                                     float* __restrict__ out) {
    const int i0 = blockIdx.x * RPC;
    const int j = threadIdx.x;
    const int lane = j & 31;
    const int w = j >> 5;

    __shared__ float Gsm[RPC][DD];
    __shared__ float red[16];
    __shared__ float norms[RPC];

#pragma unroll
    for (int r = 0; r < RPC; ++r) Gsm[r][j] = G[(size_t)(i0 + r) * DD + j];
    __syncthreads();

    float acc[RPC];
#pragma unroll
    for (int r = 0; r < RPC; ++r) acc[r] = 0.f;

#pragma unroll 4
    for (int k = 0; k < DD; ++k) {
        float wv = Wm[(size_t)k * DD + j];
#pragma unroll
        for (int r = 0; r < RPC; ++r) acc[r] = fmaf(Gsm[r][k], wv, acc[r]);
    }

    float aj = alpha[j];
#pragma unroll
    for (int r = 0; r < RPC; ++r)
        acc[r] = Wm[(size_t)(i0 + r) * DD + j] * (1.f - decay[i0 + r]) + aj * acc[r];

    for (int r = 0; r < RPC; ++r) {
        float s = acc[r] * acc[r];
#pragma unroll
        for (int o = 16; o; o >>= 1) s += __shfl_xor_sync(0xffffffffu, s, o);
        if (lane == 0) red[w] = s;
        __syncthreads();
        if (j == 0) {
            float tsum = 0.f;
#pragma unroll
            for (int q = 0; q < 16; ++q) tsum += red[q];
            norms[r] = fmaxf(sqrtf(tsum), 1e-12f);
        }
        __syncthreads();
    }

#pragma unroll
    for (int r = 0; r < RPC; ++r)
        out[(size_t)(i0 + r) * DD + j] = acc[r] / norms[r];
}

// ---------------- launch ----------------
extern "C" void kernel_launch(void* const* d_in, const int* in_sizes, int n_in,
                              void* d_out, int out_size) {
    const float* stim = (const float*)d_in[0];
    const float* prev = (const float*)d_in[1];
    const float* W    = (const float*)d_in[2];
    const float* Wr   = (const float*)d_in[3];
    const float* alpha = (const float*)d_in[4];
    const float* decay = (const float*)d_in[5];
    const float* gact = (const float*)d_in[6];
    const float* bact = (const float*)d_in[7];
    const float* grec = (const float*)d_in[8];
    const float* brec = (const float*)d_in[9];
    float* out = (float*)d_out;

    const long Brows = in_sizes[0] / DD;  // 32768

    bf16 *s_hi, *s_lo, *p_hi, *p_lo, *st_hi, *st_lo, *pt_hi, *pt_lo;
    bf16 *wt_hi, *wt_lo, *wrt_hi, *wrt_lo;
    float *stim_out, *rec_out, *partS, *partP, *GS, *GP;
    cudaGetSymbolAddress((void**)&s_hi, g_s_hi);
    cudaGetSymbolAddress((void**)&s_lo, g_s_lo);
    cudaGetSymbolAddress((void**)&p_hi, g_p_hi);
    cudaGetSymbolAddress((void**)&p_lo, g_p_lo);
    cudaGetSymbolAddress((void**)&st_hi, g_st_hi);
    cudaGetSymbolAddress((void**)&st_lo, g_st_lo);
    cudaGetSymbolAddress((void**)&pt_hi, g_pt_hi);
    cudaGetSymbolAddress((void**)&pt_lo, g_pt_lo);
    cudaGetSymbolAddress((void**)&wt_hi, g_wt_hi);
    cudaGetSymbolAddress((void**)&wt_lo, g_wt_lo);
    cudaGetSymbolAddress((void**)&wrt_hi, g_wrt_hi);
    cudaGetSymbolAddress((void**)&wrt_lo, g_wrt_lo);
    cudaGetSymbolAddress((void**)&stim_out, g_stim_out);
    cudaGetSymbolAddress((void**)&rec_out, g_rec_out);
    cudaGetSymbolAddress((void**)&partS, g_partS);
    cudaGetSymbolAddress((void**)&partP, g_partP);
    cudaGetSymbolAddress((void**)&GS, g_GS);
    cudaGetSymbolAddress((void**)&GP, g_GP);

    cudaFuncSetAttribute(mma_all, cudaFuncAttributeMaxDynamicSharedMemorySize, SMEM_DYN);

    // launch 0: fused stim prep (rm + tr)
    dim3 tb(32, 8);
    split_both<<<dim3(DD / 32, Brows / 32), tb>>>(stim, s_hi, s_lo, st_hi, st_lo, Brows, DD);
    // launches 1-2: prev prep
    long nvec = Brows * DD / 8;
    split_rm<<<nvec / 256, 256>>>((const float4*)prev, (uint4*)p_hi, (uint4*)p_lo);
    split_tr<<<dim3(DD / 32, Brows / 32), tb>>>(prev, pt_hi, pt_lo, Brows, DD);
    // launches 3-4: weight transposed preps
    split_tr<<<dim3(DD / 32, DD / 32), tb>>>(W, wt_hi, wt_lo, DD, DD);
    split_tr<<<dim3(DD / 32, DD / 32), tb>>>(Wr, wrt_hi, wrt_lo, DD, DD);

    // launch 5 (profiled by ncu -s 5): ALL four GEMMs merged
    const int fwdBlocks = (int)(Brows / MT) * (DD / NT);  // 1024
    const int gramBlocks = 10 * NSPLIT;                   // 320
    const int kcg = (int)(Brows / NSPLIT);                // 1024
    Seg4 segs;
    segs.s[0] = {s_hi, s_lo, wt_hi, wt_lo, DD, DD, stim_out, 0, DD, 0, 0};
    segs.s[1] = {p_hi, p_lo, wrt_hi, wrt_lo, DD, DD, rec_out, 0, DD, 0, fwdBlocks};
    segs.s[2] = {st_hi, st_lo, st_hi, st_lo, Brows, Brows, partS, (long)DD * DD, kcg, 1, 2 * fwdBlocks};
    segs.s[3] = {pt_hi, pt_lo, pt_hi, pt_lo, Brows, Brows, partP, (long)DD * DD, kcg, 1, 2 * fwdBlocks + gramBlocks};
    mma_all<<<2 * fwdBlocks + 2 * gramBlocks, 256, SMEM_DYN>>>(segs);

    reduce_gram<<<(DD * DD) / 256, 256>>>();

    ln_fuse<<<(unsigned)Brows, 512>>>(rec_out, stim_out, grec, brec, gact, bact, out);

    size_t off = (size_t)Brows * DD;
    weight_update<<<DD / RPC, 512>>>(W, GS, alpha, decay, out + off);
    weight_update<<<DD / RPC, 512>>>(Wr, GP, alpha, decay, out + off + (size_t)DD * DD);
}

// round 5
// speedup vs baseline: 2.2095x; 1.0708x over previous
#include <cuda_runtime.h>
#include <cuda_bf16.h>
#include <cstdint>

typedef __nv_bfloat16 bf16;

// ---------------- problem constants ----------------
#define DD 512
#define MAXB 32768
#define NSPLIT 16
#define BKT 64                         // K per stage (bf16 elems) -> 128B rows
#define MT 128
#define NT 128
#define TILE_B (MT * BKT * 2)          // 16384 bytes per operand tile
#define STAGE_B (4 * TILE_B)           // 65536 (Ahi, Alo, Bhi, Blo)
#define NSTAGE 3
#define SMEM_DYN (NSTAGE * STAGE_B + 128)

// ---------------- scratch (device globals; no allocation) ----------------
__device__ __align__(256) bf16 g_s_hi[(size_t)MAXB * DD];
__device__ __align__(256) bf16 g_s_lo[(size_t)MAXB * DD];
__device__ __align__(256) bf16 g_p_hi[(size_t)MAXB * DD];
__device__ __align__(256) bf16 g_p_lo[(size_t)MAXB * DD];
__device__ __align__(256) bf16 g_st_hi[(size_t)DD * MAXB];
__device__ __align__(256) bf16 g_st_lo[(size_t)DD * MAXB];
__device__ __align__(256) bf16 g_pt_hi[(size_t)DD * MAXB];
__device__ __align__(256) bf16 g_pt_lo[(size_t)DD * MAXB];
__device__ __align__(256) bf16 g_wt_hi[DD * DD];
__device__ __align__(256) bf16 g_wt_lo[DD * DD];
__device__ __align__(256) bf16 g_wrt_hi[DD * DD];
__device__ __align__(256) bf16 g_wrt_lo[DD * DD];
__device__ __align__(256) float g_stim_out[(size_t)MAXB * DD];
__device__ __align__(256) float g_rec_out[(size_t)MAXB * DD];
__device__ __align__(256) float g_partS[(size_t)NSPLIT * DD * DD];
__device__ __align__(256) float g_partP[(size_t)NSPLIT * DD * DD];
__device__ __align__(256) float g_GS[DD * DD];
__device__ __align__(256) float g_GP[DD * DD];

// ---------------- PTX helpers (base-ISA only: sm_80+ safe) ----------------
__device__ __forceinline__ uint32_t smem_u32(const void* p) {
    uint32_t a;
    asm("{ .reg .u64 t; cvta.to.shared.u64 t, %1; cvt.u32.u64 %0, t; }" : "=r"(a) : "l"(p));
    return a;
}
__device__ __forceinline__ void ldsm_x4(uint32_t* r, uint32_t addr) {
    asm volatile("ldmatrix.sync.aligned.m8n8.x4.shared.b16 {%0,%1,%2,%3}, [%4];"
                 : "=r"(r[0]), "=r"(r[1]), "=r"(r[2]), "=r"(r[3]) : "r"(addr));
}
__device__ __forceinline__ void mma16816(float* c, const uint32_t* a, uint32_t b0, uint32_t b1) {
    asm volatile(
        "mma.sync.aligned.m16n8k16.row.col.f32.bf16.bf16.f32 "
        "{%0,%1,%2,%3}, {%4,%5,%6,%7}, {%8,%9}, {%0,%1,%2,%3};"
        : "+f"(c[0]), "+f"(c[1]), "+f"(c[2]), "+f"(c[3])
        : "r"(a[0]), "r"(a[1]), "r"(a[2]), "r"(a[3]), "r"(b0), "r"(b1));
}
__device__ __forceinline__ void cp16(uint32_t dst, const void* src) {
    asm volatile("cp.async.cg.shared.global [%0], [%1], 16;" :: "r"(dst), "l"(src) : "memory");
}
#define CP_COMMIT() asm volatile("cp.async.commit_group;" ::: "memory")

// swizzled smem byte offset within a tile: 128B rows, 8 x 16B chunks, chunk xor (row&7)
__device__ __forceinline__ uint32_t swz(int row, int chunk) {
    return (uint32_t)(row * 128 + ((chunk ^ (row & 7)) << 4));
}

// ---------------- segment descriptor for the merged GEMM launch ----------------
struct Seg {
    const bf16 *Ah, *Al, *Bh, *Bl;
    long lda, ldb;
    float* C;
    long pstride;
    int kc;     // K per block (split-K chunk for gram, full K for forward)
    int gram;   // 0: forward tiling, 1: upper-tri gram tiling
    int blk0;   // first global block id of this segment
};
struct Seg4 { Seg s[4]; };

// ---------------- stage loader: 4 tiles (Ahi, Alo, Bhi, Blo), cp.async ----------------
__device__ __forceinline__ void load_stage(uint32_t sb,
                                           const bf16* __restrict__ Ahi, const bf16* __restrict__ Alo,
                                           const bf16* __restrict__ Bhi, const bf16* __restrict__ Blo,
                                           long lda, long ldb, long m0, long n0, long k0, int tid) {
    const bf16* ptrs[4] = {Ahi + m0 * lda + k0, Alo + m0 * lda + k0,
                           Bhi + n0 * ldb + k0, Blo + n0 * ldb + k0};
#pragma unroll
    for (int t = 0; t < 4; ++t) {
        long ld = (t < 2) ? lda : ldb;
        uint32_t tb = sb + t * TILE_B;
#pragma unroll
        for (int q = 0; q < 4; ++q) {
            int ci = tid + q * 256;       // 0..1023 chunk index (128 rows x 8 chunks)
            int row = ci >> 3, c = ci & 7;
            cp16(tb + swz(row, c), ptrs[t] + (long)row * ld + c * 8);
        }
    }
    CP_COMMIT();
}

// ---------------- merged mma.sync GEMM: all 4 GEMMs in one launch ----------------
__global__ __launch_bounds__(256, 1)
void mma_all(Seg4 segs) {
    extern __shared__ char smraw[];
    const uint32_t base = (smem_u32(smraw) + 127u) & ~127u;

    const int bid = blockIdx.x;
    int si = (bid >= segs.s[2].blk0) ? ((bid >= segs.s[3].blk0) ? 3 : 2)
                                     : ((bid >= segs.s[1].blk0) ? 1 : 0);
    const Seg sg = segs.s[si];
    const int b = bid - sg.blk0;

    const int tid = threadIdx.x;
    const int lane = tid & 31;
    const int wid = tid >> 5;
    const int wm = wid & 1;        // 2 warp-rows of 64
    const int wn = wid >> 1;       // 4 warp-cols of 32
    const int r15 = lane & 15;
    const int hi4 = lane >> 4;

    long m0, n0, kbase;
    float* C = sg.C;
    if (sg.gram) {
        const int PI[10] = {0, 0, 0, 0, 1, 1, 1, 2, 2, 3};
        const int PJ[10] = {0, 1, 2, 3, 1, 2, 3, 2, 3, 3};
        int p = b % 10, z = b / 10;
        m0 = (long)PI[p] * MT;
        n0 = (long)PJ[p] * NT;
        kbase = (long)z * sg.kc;
        C += (long)z * sg.pstride;
    } else {
        m0 = (long)(b >> 2) * MT;
        n0 = (long)(b & 3) * NT;
        kbase = 0;
    }
    const int niter = sg.kc / BKT;

    float acc[4][4][4];
#pragma unroll
    for (int i = 0; i < 4; ++i)
#pragma unroll
        for (int j = 0; j < 4; ++j)
#pragma unroll
            for (int q = 0; q < 4; ++q) acc[i][j][q] = 0.f;

    // prologue: fill NSTAGE-1 stages
    load_stage(base, sg.Ah, sg.Al, sg.Bh, sg.Bl, sg.lda, sg.ldb, m0, n0, kbase, tid);
    load_stage(base + STAGE_B, sg.Ah, sg.Al, sg.Bh, sg.Bl, sg.lda, sg.ldb, m0, n0, kbase + BKT, tid);

    for (int i = 0; i < niter; ++i) {
        if (i + 1 < niter) asm volatile("cp.async.wait_group 1;" ::: "memory");
        else               asm volatile("cp.async.wait_group 0;" ::: "memory");
        __syncthreads();

        if (i + 2 < niter)
            load_stage(base + ((i + 2) % NSTAGE) * STAGE_B, sg.Ah, sg.Al, sg.Bh, sg.Bl,
                       sg.lda, sg.ldb, m0, n0, kbase + (long)(i + 2) * BKT, tid);

        const uint32_t sb = base + (i % NSTAGE) * STAGE_B;
        const uint32_t Ah = sb, Al = sb + TILE_B, Bh = sb + 2 * TILE_B, Bl = sb + 3 * TILE_B;

#pragma unroll
        for (int ks = 0; ks < 4; ++ks) {
            uint32_t ah[4][4], al[4][4], bh[2][4], bl[2][4];
#pragma unroll
            for (int mt = 0; mt < 4; ++mt) {
                int row = wm * 64 + mt * 16 + r15;
                int ck = 2 * ks + hi4;
                ldsm_x4(ah[mt], Ah + swz(row, ck));
                ldsm_x4(al[mt], Al + swz(row, ck));
            }
#pragma unroll
            for (int np = 0; np < 2; ++np) {
                int row = wn * 32 + np * 16 + r15;
                int ck = 2 * ks + hi4;
                ldsm_x4(bh[np], Bh + swz(row, ck));
                ldsm_x4(bl[np], Bl + swz(row, ck));
            }
#pragma unroll
            for (int mt = 0; mt < 4; ++mt)
#pragma unroll
                for (int nt = 0; nt < 4; ++nt) {
                    int np = nt >> 1, p = nt & 1;
                    mma16816(acc[mt][nt], ah[mt], bh[np][p], bh[np][p + 2]);
                    mma16816(acc[mt][nt], ah[mt], bl[np][p], bl[np][p + 2]);
                    mma16816(acc[mt][nt], al[mt], bh[np][p], bh[np][p + 2]);
                }
        }
    }

    // epilogue: write fp32 directly from accumulators
#pragma unroll
    for (int mt = 0; mt < 4; ++mt) {
        long row = m0 + wm * 64 + mt * 16 + (lane >> 2);
#pragma unroll
        for (int nt = 0; nt < 4; ++nt) {
            long col = n0 + wn * 32 + nt * 8 + 2 * (lane & 3);
            *(float2*)&C[row * DD + col] = make_float2(acc[mt][nt][0], acc[mt][nt][1]);
            *(float2*)&C[(row + 8) * DD + col] = make_float2(acc[mt][nt][2], acc[mt][nt][3]);
        }
    }
}

// ------- fused prep: row-major hi/lo AND transposed hi/lo from one read -------
__global__ __launch_bounds__(256) void split_both(const float* __restrict__ X,
                                                  bf16* __restrict__ Hr, bf16* __restrict__ Lr,
                                                  bf16* __restrict__ Th, bf16* __restrict__ Tl,
                                                  long R, long C) {
    __shared__ float s[32][33];
    const int tx = threadIdx.x, ty = threadIdx.y;
    const long c0 = (long)blockIdx.x * 32, r0 = (long)blockIdx.y * 32;
#pragma unroll
    for (int i = 0; i < 4; ++i) {
        long row = r0 + ty + 8 * i;
        float v = X[row * C + c0 + tx];
        s[tx][ty + 8 * i] = v;
        bf16 hb = __float2bfloat16(v);
        long o = row * C + c0 + tx;
        Hr[o] = hb;
        Lr[o] = __float2bfloat16(v - __bfloat162float(hb));
    }
    __syncthreads();
#pragma unroll
    for (int i = 0; i < 4; ++i) {
        float v = s[ty + 8 * i][tx];
        bf16 hb = __float2bfloat16(v);
        long o = (c0 + ty + 8 * i) * R + r0 + tx;
        Th[o] = hb;
        Tl[o] = __float2bfloat16(v - __bfloat162float(hb));
    }
}

// ------- combined W + Wr transposed split in one launch (grid.z selects) -------
__global__ __launch_bounds__(256) void split_w2(const float* __restrict__ W0,
                                                const float* __restrict__ W1,
                                                bf16* __restrict__ Th0, bf16* __restrict__ Tl0,
                                                bf16* __restrict__ Th1, bf16* __restrict__ Tl1) {
    __shared__ float s[32][33];
    const int tx = threadIdx.x, ty = threadIdx.y;
    const long c0 = (long)blockIdx.x * 32, r0 = (long)blockIdx.y * 32;
    const float* X = blockIdx.z ? W1 : W0;
    bf16* Th = blockIdx.z ? Th1 : Th0;
    bf16* Tl = blockIdx.z ? Tl1 : Tl0;
#pragma unroll
    for (int i = 0; i < 4; ++i)
        s[tx][ty + 8 * i] = X[(r0 + ty + 8 * i) * DD + c0 + tx];
    __syncthreads();
#pragma unroll
    for (int i = 0; i < 4; ++i) {
        float v = s[ty + 8 * i][tx];
        bf16 hb = __float2bfloat16(v);
        long o = (c0 + ty + 8 * i) * DD + r0 + tx;
        Th[o] = hb;
        Tl[o] = __float2bfloat16(v - __bfloat162float(hb));
    }
}

// ---------------- reduce split-K Gram partials (symmetric mirror) ----------------
__global__ void reduce_gram() {
    int idx = blockIdx.x * blockDim.x + threadIdx.x;
    int i = idx >> 9, j = idx & 511;
    size_t src = ((i >> 7) <= (j >> 7)) ? ((size_t)i * DD + j) : ((size_t)j * DD + i);
    float s = 0.f, p = 0.f;
#pragma unroll 8
    for (int z = 0; z < NSPLIT; ++z) {
        s += g_partS[(size_t)z * DD * DD + src];
        p += g_partP[(size_t)z * DD * DD + src];
    }
    g_GS[idx] = s;
    g_GP[idx] = p;
}

// ---------------- fused LN(rec) -> add stim -> relu -> LN(act) ----------------
__global__ __launch_bounds__(512) void ln_fuse(const float* __restrict__ rec,
                                               const float* __restrict__ stim,
                                               const float* __restrict__ grec,
                                               const float* __restrict__ brec,
                                               const float* __restrict__ gact,
                                               const float* __restrict__ bact,
                                               float* __restrict__ out) {
    const int row = blockIdx.x;
    const int t = threadIdx.x;
    const int lane = t & 31;
    const int w = t >> 5;
    __shared__ float r1[32], r2[32], s1[32], s2[32];

    float x = rec[(size_t)row * DD + t];
    float a = x, b = x * x;
#pragma unroll
    for (int o = 16; o; o >>= 1) {
        a += __shfl_xor_sync(0xffffffffu, a, o);
        b += __shfl_xor_sync(0xffffffffu, b, o);
    }
    if (lane == 0) { r1[w] = a; r2[w] = b; }
    __syncthreads();
    if (w == 0) {
        a = (lane < 16) ? r1[lane] : 0.f;
        b = (lane < 16) ? r2[lane] : 0.f;
#pragma unroll
        for (int o = 16; o; o >>= 1) {
            a += __shfl_xor_sync(0xffffffffu, a, o);
            b += __shfl_xor_sync(0xffffffffu, b, o);
        }
        if (lane == 0) { r1[0] = a; r2[0] = b; }
    }
    __syncthreads();
    float mu = r1[0] * (1.f / DD);
    float var = r2[0] * (1.f / DD) - mu * mu;
    float rn = (x - mu) * rsqrtf(var + 1e-5f) * grec[t] + brec[t];

    float v = fmaxf(stim[(size_t)row * DD + t] + rn, 0.f);
    a = v;
    b = v * v;
#pragma unroll
    for (int o = 16; o; o >>= 1) {
        a += __shfl_xor_sync(0xffffffffu, a, o);
        b += __shfl_xor_sync(0xffffffffu, b, o);
    }
    if (lane == 0) { s1[w] = a; s2[w] = b; }
    __syncthreads();
    if (w == 0) {
        a = (lane < 16) ? s1[lane] : 0.f;
        b = (lane < 16) ? s2[lane] : 0.f;
#pragma unroll
        for (int o = 16; o; o >>= 1) {
            a += __shfl_xor_sync(0xffffffffu, a, o);
            b += __shfl_xor_sync(0xffffffffu, b, o);
        }
        if (lane == 0) { s1[0] = a; s2[0] = b; }
    }
    __syncthreads();
    float mu2 = s1[0] * (1.f / DD);
    float var2 = s2[0] * (1.f / DD) - mu2 * mu2;
    out[(size_t)row * DD + t] = (v - mu2) * rsqrtf(var2 + 1e-5f) * gact[t] + bact[t];
}

// ---------- weight update: out = l2norm_rows(W*(1-decay_i) + alpha_j*(G@W)) ----------
#define RPC 8
__global__ __launch_bounds__(512) void weight_update(const float* __restrict__ Wm,
                                                     const float* __restrict__ G,
                                                     const float* __restrict__ alpha,
                                                     const float* __restrict__ decay,
                                                     float* __restrict__ out) {
    const int i0 = blockIdx.x * RPC;
    const int j = threadIdx.x;
    const int lane = j & 31;
    const int w = j >> 5;

    __shared__ float Gsm[RPC][DD];
    __shared__ float red[16];
    __shared__ float norms[RPC];

#pragma unroll
    for (int r = 0; r < RPC; ++r) Gsm[r][j] = G[(size_t)(i0 + r) * DD + j];
    __syncthreads();

    float acc[RPC];
#pragma unroll
    for (int r = 0; r < RPC; ++r) acc[r] = 0.f;

#pragma unroll 4
    for (int k = 0; k < DD; ++k) {
        float wv = Wm[(size_t)k * DD + j];
#pragma unroll
        for (int r = 0; r < RPC; ++r) acc[r] = fmaf(Gsm[r][k], wv, acc[r]);
    }

    float aj = alpha[j];
#pragma unroll
    for (int r = 0; r < RPC; ++r)
        acc[r] = Wm[(size_t)(i0 + r) * DD + j] * (1.f - decay[i0 + r]) + aj * acc[r];

    for (int r = 0; r < RPC; ++r) {
        float s = acc[r] * acc[r];
#pragma unroll
        for (int o = 16; o; o >>= 1) s += __shfl_xor_sync(0xffffffffu, s, o);
        if (lane == 0) red[w] = s;
        __syncthreads();
        if (j == 0) {
            float tsum = 0.f;
#pragma unroll
            for (int q = 0; q < 16; ++q) tsum += red[q];
            norms[r] = fmaxf(sqrtf(tsum), 1e-12f);
        }
        __syncthreads();
    }

#pragma unroll
    for (int r = 0; r < RPC; ++r)
        out[(size_t)(i0 + r) * DD + j] = acc[r] / norms[r];
}

// ---------------- launch ----------------
extern "C" void kernel_launch(void* const* d_in, const int* in_sizes, int n_in,
                              void* d_out, int out_size) {
    const float* stim = (const float*)d_in[0];
    const float* prev = (const float*)d_in[1];
    const float* W    = (const float*)d_in[2];
    const float* Wr   = (const float*)d_in[3];
    const float* alpha = (const float*)d_in[4];
    const float* decay = (const float*)d_in[5];
    const float* gact = (const float*)d_in[6];
    const float* bact = (const float*)d_in[7];
    const float* grec = (const float*)d_in[8];
    const float* brec = (const float*)d_in[9];
    float* out = (float*)d_out;

    const long Brows = in_sizes[0] / DD;  // 32768

    bf16 *s_hi, *s_lo, *p_hi, *p_lo, *st_hi, *st_lo, *pt_hi, *pt_lo;
    bf16 *wt_hi, *wt_lo, *wrt_hi, *wrt_lo;
    float *stim_out, *rec_out, *partS, *partP, *GS, *GP;
    cudaGetSymbolAddress((void**)&s_hi, g_s_hi);
    cudaGetSymbolAddress((void**)&s_lo, g_s_lo);
    cudaGetSymbolAddress((void**)&p_hi, g_p_hi);
    cudaGetSymbolAddress((void**)&p_lo, g_p_lo);
    cudaGetSymbolAddress((void**)&st_hi, g_st_hi);
    cudaGetSymbolAddress((void**)&st_lo, g_st_lo);
    cudaGetSymbolAddress((void**)&pt_hi, g_pt_hi);
    cudaGetSymbolAddress((void**)&pt_lo, g_pt_lo);
    cudaGetSymbolAddress((void**)&wt_hi, g_wt_hi);
    cudaGetSymbolAddress((void**)&wt_lo, g_wt_lo);
    cudaGetSymbolAddress((void**)&wrt_hi, g_wrt_hi);
    cudaGetSymbolAddress((void**)&wrt_lo, g_wrt_lo);
    cudaGetSymbolAddress((void**)&stim_out, g_stim_out);
    cudaGetSymbolAddress((void**)&rec_out, g_rec_out);
    cudaGetSymbolAddress((void**)&partS, g_partS);
    cudaGetSymbolAddress((void**)&partP, g_partP);
    cudaGetSymbolAddress((void**)&GS, g_GS);
    cudaGetSymbolAddress((void**)&GP, g_GP);

    cudaFuncSetAttribute(mma_all, cudaFuncAttributeMaxDynamicSharedMemorySize, SMEM_DYN);

    // launches 0-2: prep (exactly 3 launches so mma_all sits at index 3 for ncu)
    dim3 tb(32, 8);
    split_both<<<dim3(DD / 32, Brows / 32), tb>>>(stim, s_hi, s_lo, st_hi, st_lo, Brows, DD);
    split_both<<<dim3(DD / 32, Brows / 32), tb>>>(prev, p_hi, p_lo, pt_hi, pt_lo, Brows, DD);
    split_w2<<<dim3(DD / 32, DD / 32, 2), tb>>>(W, Wr, wt_hi, wt_lo, wrt_hi, wrt_lo);

    // launch 3 (ncu capture slot): ALL four GEMMs merged, gram blocks first (LPT order)
    const int fwdBlocks = (int)(Brows / MT) * (DD / NT);  // 1024
    const int gramBlocks = 10 * NSPLIT;                   // 160
    const int kcg = (int)(Brows / NSPLIT);                // 2048
    Seg4 segs;
    segs.s[0] = {st_hi, st_lo, st_hi, st_lo, Brows, Brows, partS, (long)DD * DD, kcg, 1, 0};
    segs.s[1] = {pt_hi, pt_lo, pt_hi, pt_lo, Brows, Brows, partP, (long)DD * DD, kcg, 1, gramBlocks};
    segs.s[2] = {s_hi, s_lo, wt_hi, wt_lo, DD, DD, stim_out, 0, DD, 0, 2 * gramBlocks};
    segs.s[3] = {p_hi, p_lo, wrt_hi, wrt_lo, DD, DD, rec_out, 0, DD, 0, 2 * gramBlocks + fwdBlocks};
    mma_all<<<2 * gramBlocks + 2 * fwdBlocks, 256, SMEM_DYN>>>(segs);

    reduce_gram<<<(DD * DD) / 256, 256>>>();

    ln_fuse<<<(unsigned)Brows, 512>>>(rec_out, stim_out, grec, brec, gact, bact, out);

    size_t off = (size_t)Brows * DD;
    weight_update<<<DD / RPC, 512>>>(W, GS, alpha, decay, out + off);
    weight_update<<<DD / RPC, 512>>>(Wr, GP, alpha, decay, out + off + (size_t)DD * DD);
}

// round 6
// speedup vs baseline: 2.8708x; 1.2993x over previous
#include <cuda_runtime.h>
#include <cuda_bf16.h>
#include <cstdint>

typedef __nv_bfloat16 bf16;

// ---------------- problem constants ----------------
#define DD 512
#define MAXB 32768
#define NSPLIT 16
#define BKT 64                          // K per stage -> 128B rows
#define MT 128
#define NT 64
#define TILE_A (MT * BKT * 2)           // 16384 B
#define TILE_BB (NT * BKT * 2)          // 8192 B
#define STAGE_B (2 * TILE_A + 2 * TILE_BB)  // 49152 B
#define SMEM_DYN (2 * STAGE_B + 128)        // 98432 B -> 2 CTAs/SM

// ---------------- scratch (device globals; no allocation) ----------------
__device__ __align__(256) bf16 g_s_hi[(size_t)MAXB * DD];
__device__ __align__(256) bf16 g_s_lo[(size_t)MAXB * DD];
__device__ __align__(256) bf16 g_p_hi[(size_t)MAXB * DD];
__device__ __align__(256) bf16 g_p_lo[(size_t)MAXB * DD];
__device__ __align__(256) bf16 g_st_hi[(size_t)DD * MAXB];
__device__ __align__(256) bf16 g_st_lo[(size_t)DD * MAXB];
__device__ __align__(256) bf16 g_pt_hi[(size_t)DD * MAXB];
__device__ __align__(256) bf16 g_pt_lo[(size_t)DD * MAXB];
__device__ __align__(256) bf16 g_wt_hi[DD * DD];
__device__ __align__(256) bf16 g_wt_lo[DD * DD];
__device__ __align__(256) bf16 g_wrt_hi[DD * DD];
__device__ __align__(256) bf16 g_wrt_lo[DD * DD];
__device__ __align__(256) float g_stim_out[(size_t)MAXB * DD];
__device__ __align__(256) float g_rec_out[(size_t)MAXB * DD];
__device__ __align__(256) float g_partS[(size_t)NSPLIT * DD * DD];
__device__ __align__(256) float g_partP[(size_t)NSPLIT * DD * DD];
__device__ __align__(256) float g_GS[DD * DD];
__device__ __align__(256) float g_GP[DD * DD];

// ---------------- PTX helpers (base-ISA only: sm_80+ safe) ----------------
__device__ __forceinline__ uint32_t smem_u32(const void* p) {
    uint32_t a;
    asm("{ .reg .u64 t; cvta.to.shared.u64 t, %1; cvt.u32.u64 %0, t; }" : "=r"(a) : "l"(p));
    return a;
}
__device__ __forceinline__ void ldsm_x4(uint32_t* r, uint32_t addr) {
    asm volatile("ldmatrix.sync.aligned.m8n8.x4.shared.b16 {%0,%1,%2,%3}, [%4];"
                 : "=r"(r[0]), "=r"(r[1]), "=r"(r[2]), "=r"(r[3]) : "r"(addr));
}
__device__ __forceinline__ void mma16816(float* c, const uint32_t* a, uint32_t b0, uint32_t b1) {
    asm volatile(
        "mma.sync.aligned.m16n8k16.row.col.f32.bf16.bf16.f32 "
        "{%0,%1,%2,%3}, {%4,%5,%6,%7}, {%8,%9}, {%0,%1,%2,%3};"
        : "+f"(c[0]), "+f"(c[1]), "+f"(c[2]), "+f"(c[3])
        : "r"(a[0]), "r"(a[1]), "r"(a[2]), "r"(a[3]), "r"(b0), "r"(b1));
}
__device__ __forceinline__ void cp16(uint32_t dst, const void* src) {
    asm volatile("cp.async.cg.shared.global [%0], [%1], 16;" :: "r"(dst), "l"(src) : "memory");
}
#define CP_COMMIT() asm volatile("cp.async.commit_group;" ::: "memory")

// swizzled smem byte offset within a tile: 128B rows, 8 x 16B chunks, chunk xor (row&7)
__device__ __forceinline__ uint32_t swz(int row, int chunk) {
    return (uint32_t)(row * 128 + ((chunk ^ (row & 7)) << 4));
}

// ---------------- segment descriptor for the merged GEMM launch ----------------
struct Seg {
    const bf16 *Ah, *Al, *Bh, *Bl;
    long lda, ldb;
    float* C;
    long pstride;
    int kc;     // K per block
    int gram;   // 0: forward tiling, 1: upper-tri gram tiling
    int blk0;   // first global block id of this segment
};
struct Seg4 { Seg s[4]; };

// ---------------- stage loader: Ahi(128), Alo(128), Bhi(64), Blo(64) rows ----------------
__device__ __forceinline__ void load_stage(uint32_t sb,
                                           const bf16* __restrict__ Ahi, const bf16* __restrict__ Alo,
                                           const bf16* __restrict__ Bhi, const bf16* __restrict__ Blo,
                                           long lda, long ldb, long m0, long n0, long k0, int tid) {
    const bf16* pAh = Ahi + m0 * lda + k0;
    const bf16* pAl = Alo + m0 * lda + k0;
    const bf16* pBh = Bhi + n0 * ldb + k0;
    const bf16* pBl = Blo + n0 * ldb + k0;
    // A tiles: 128 rows x 8 chunks = 1024 chunks each -> 4 iters per tile
#pragma unroll
    for (int q = 0; q < 4; ++q) {
        int ci = tid + q * 256;
        int row = ci >> 3, c = ci & 7;
        cp16(sb + swz(row, c), pAh + (long)row * lda + c * 8);
    }
#pragma unroll
    for (int q = 0; q < 4; ++q) {
        int ci = tid + q * 256;
        int row = ci >> 3, c = ci & 7;
        cp16(sb + TILE_A + swz(row, c), pAl + (long)row * lda + c * 8);
    }
    // B tiles: 64 rows x 8 chunks = 512 chunks each -> 2 iters per tile
#pragma unroll
    for (int q = 0; q < 2; ++q) {
        int ci = tid + q * 256;
        int row = ci >> 3, c = ci & 7;
        cp16(sb + 2 * TILE_A + swz(row, c), pBh + (long)row * ldb + c * 8);
    }
#pragma unroll
    for (int q = 0; q < 2; ++q) {
        int ci = tid + q * 256;
        int row = ci >> 3, c = ci & 7;
        cp16(sb + 2 * TILE_A + TILE_BB + swz(row, c), pBl + (long)row * ldb + c * 8);
    }
    CP_COMMIT();
}

// ---------------- merged mma.sync GEMM: all 4 GEMMs in one launch ----------------
__global__ __launch_bounds__(256, 2)
void mma_all(Seg4 segs) {
    extern __shared__ char smraw[];
    const uint32_t base = (smem_u32(smraw) + 127u) & ~127u;

    const int bid = blockIdx.x;
    int si = (bid >= segs.s[2].blk0) ? ((bid >= segs.s[3].blk0) ? 3 : 2)
                                     : ((bid >= segs.s[1].blk0) ? 1 : 0);
    const Seg sg = segs.s[si];
    const int b = bid - sg.blk0;

    const int tid = threadIdx.x;
    const int lane = tid & 31;
    const int wid = tid >> 5;
    const int wm = wid >> 1;       // 4 warp-rows of 32
    const int wn = wid & 1;        // 2 warp-cols of 32
    const int r15 = lane & 15;
    const int hi4 = lane >> 4;

    long m0, n0, kbase;
    float* C = sg.C;
    if (sg.gram) {
        // 20 upper-tri (128-granular) tiles of shape 128x64
        const int PI[20] = {0,0, 0,0, 0,0, 0,0, 1,1, 1,1, 1,1, 2,2, 2,2, 3,3};
        const int PN[20] = {0,1, 2,3, 4,5, 6,7, 2,3, 4,5, 6,7, 4,5, 6,7, 6,7};
        int p = b % 20, z = b / 20;
        m0 = (long)PI[p] * MT;
        n0 = (long)PN[p] * NT;
        kbase = (long)z * sg.kc;
        C += (long)z * sg.pstride;
    } else {
        m0 = (long)(b >> 3) * MT;
        n0 = (long)(b & 7) * NT;
        kbase = 0;
    }
    const int niter = sg.kc / BKT;

    float acc[2][4][4];
#pragma unroll
    for (int i = 0; i < 2; ++i)
#pragma unroll
        for (int j = 0; j < 4; ++j)
#pragma unroll
            for (int q = 0; q < 4; ++q) acc[i][j][q] = 0.f;

    // prologue
    load_stage(base, sg.Ah, sg.Al, sg.Bh, sg.Bl, sg.lda, sg.ldb, m0, n0, kbase, tid);

    for (int i = 0; i < niter; ++i) {
        asm volatile("cp.async.wait_group 0;" ::: "memory");
        __syncthreads();

        if (i + 1 < niter)
            load_stage(base + ((i + 1) & 1) * STAGE_B, sg.Ah, sg.Al, sg.Bh, sg.Bl,
                       sg.lda, sg.ldb, m0, n0, kbase + (long)(i + 1) * BKT, tid);

        const uint32_t sb = base + (i & 1) * STAGE_B;
        const uint32_t Ah = sb, Al = sb + TILE_A;
        const uint32_t Bh = sb + 2 * TILE_A, Bl = sb + 2 * TILE_A + TILE_BB;

#pragma unroll
        for (int ks = 0; ks < 4; ++ks) {
            uint32_t ah[2][4], al[2][4], bh[2][4], bl[2][4];
            int ck = 2 * ks + hi4;
#pragma unroll
            for (int mt = 0; mt < 2; ++mt) {
                int row = wm * 32 + mt * 16 + r15;
                ldsm_x4(ah[mt], Ah + swz(row, ck));
                ldsm_x4(al[mt], Al + swz(row, ck));
            }
#pragma unroll
            for (int np = 0; np < 2; ++np) {
                int row = wn * 32 + np * 16 + r15;
                ldsm_x4(bh[np], Bh + swz(row, ck));
                ldsm_x4(bl[np], Bl + swz(row, ck));
            }
#pragma unroll
            for (int mt = 0; mt < 2; ++mt)
#pragma unroll
                for (int nt = 0; nt < 4; ++nt) {
                    int np = nt >> 1, p = nt & 1;
                    mma16816(acc[mt][nt], ah[mt], bh[np][p], bh[np][p + 2]);
                    mma16816(acc[mt][nt], ah[mt], bl[np][p], bl[np][p + 2]);
                    mma16816(acc[mt][nt], al[mt], bh[np][p], bh[np][p + 2]);
                }
        }
        __syncthreads();
    }

    // epilogue: write fp32 directly from accumulators
#pragma unroll
    for (int mt = 0; mt < 2; ++mt) {
        long row = m0 + wm * 32 + mt * 16 + (lane >> 2);
#pragma unroll
        for (int nt = 0; nt < 4; ++nt) {
            long col = n0 + wn * 32 + nt * 8 + 2 * (lane & 3);
            *(float2*)&C[row * DD + col] = make_float2(acc[mt][nt][0], acc[mt][nt][1]);
            *(float2*)&C[(row + 8) * DD + col] = make_float2(acc[mt][nt][2], acc[mt][nt][3]);
        }
    }
}

// ------- fused prep: row-major hi/lo AND transposed hi/lo from one read -------
__global__ __launch_bounds__(256) void split_both(const float* __restrict__ X,
                                                  bf16* __restrict__ Hr, bf16* __restrict__ Lr,
                                                  bf16* __restrict__ Th, bf16* __restrict__ Tl,
                                                  long R, long C) {
    __shared__ float s[32][33];
    const int tx = threadIdx.x, ty = threadIdx.y;
    const long c0 = (long)blockIdx.x * 32, r0 = (long)blockIdx.y * 32;
#pragma unroll
    for (int i = 0; i < 4; ++i) {
        long row = r0 + ty + 8 * i;
        float v = X[row * C + c0 + tx];
        s[tx][ty + 8 * i] = v;
        bf16 hb = __float2bfloat16(v);
        long o = row * C + c0 + tx;
        Hr[o] = hb;
        Lr[o] = __float2bfloat16(v - __bfloat162float(hb));
    }
    __syncthreads();
#pragma unroll
    for (int i = 0; i < 4; ++i) {
        float v = s[ty + 8 * i][tx];
        bf16 hb = __float2bfloat16(v);
        long o = (c0 + ty + 8 * i) * R + r0 + tx;
        Th[o] = hb;
        Tl[o] = __float2bfloat16(v - __bfloat162float(hb));
    }
}

// ------- combined W + Wr transposed split in one launch (grid.z selects) -------
__global__ __launch_bounds__(256) void split_w2(const float* __restrict__ W0,
                                                const float* __restrict__ W1,
                                                bf16* __restrict__ Th0, bf16* __restrict__ Tl0,
                                                bf16* __restrict__ Th1, bf16* __restrict__ Tl1) {
    __shared__ float s[32][33];
    const int tx = threadIdx.x, ty = threadIdx.y;
    const long c0 = (long)blockIdx.x * 32, r0 = (long)blockIdx.y * 32;
    const float* X = blockIdx.z ? W1 : W0;
    bf16* Th = blockIdx.z ? Th1 : Th0;
    bf16* Tl = blockIdx.z ? Tl1 : Tl0;
#pragma unroll
    for (int i = 0; i < 4; ++i)
        s[tx][ty + 8 * i] = X[(r0 + ty + 8 * i) * DD + c0 + tx];
    __syncthreads();
#pragma unroll
    for (int i = 0; i < 4; ++i) {
        float v = s[ty + 8 * i][tx];
        bf16 hb = __float2bfloat16(v);
        long o = (c0 + ty + 8 * i) * DD + r0 + tx;
        Th[o] = hb;
        Tl[o] = __float2bfloat16(v - __bfloat162float(hb));
    }
}

// ---------------- reduce split-K Gram partials (symmetric mirror, 128-granular) ----------------
__global__ void reduce_gram() {
    int idx = blockIdx.x * blockDim.x + threadIdx.x;
    int i = idx >> 9, j = idx & 511;
    size_t src = ((i >> 7) <= (j >> 7)) ? ((size_t)i * DD + j) : ((size_t)j * DD + i);
    float s = 0.f, p = 0.f;
#pragma unroll 8
    for (int z = 0; z < NSPLIT; ++z) {
        s += g_partS[(size_t)z * DD * DD + src];
        p += g_partP[(size_t)z * DD * DD + src];
    }
    g_GS[idx] = s;
    g_GP[idx] = p;
}

// ---------------- warp-per-row fused LN(rec) -> add stim -> relu -> LN(act) ----------------
__global__ __launch_bounds__(256) void ln_fuse(const float* __restrict__ rec,
                                               const float* __restrict__ stim,
                                               const float* __restrict__ grec,
                                               const float* __restrict__ brec,
                                               const float* __restrict__ gact,
                                               const float* __restrict__ bact,
                                               float* __restrict__ out) {
    const int lane = threadIdx.x & 31;
    const long row = (long)blockIdx.x * 8 + (threadIdx.x >> 5);
    const float* rr = rec + row * DD;
    const float* sr = stim + row * DD;
    float* orow = out + row * DD;

    float x[16];
    float a = 0.f, bsum = 0.f;
#pragma unroll
    for (int e = 0; e < 16; ++e) {
        x[e] = rr[e * 32 + lane];
        a += x[e];
        bsum += x[e] * x[e];
    }
#pragma unroll
    for (int o = 16; o; o >>= 1) {
        a += __shfl_xor_sync(0xffffffffu, a, o);
        bsum += __shfl_xor_sync(0xffffffffu, bsum, o);
    }
    float mu = a * (1.f / DD);
    float var = bsum * (1.f / DD) - mu * mu;
    float rstd = rsqrtf(var + 1e-5f);

    float v[16];
    a = 0.f; bsum = 0.f;
#pragma unroll
    for (int e = 0; e < 16; ++e) {
        int c = e * 32 + lane;
        float rn = (x[e] - mu) * rstd * grec[c] + brec[c];
        v[e] = fmaxf(sr[c] + rn, 0.f);
        a += v[e];
        bsum += v[e] * v[e];
    }
#pragma unroll
    for (int o = 16; o; o >>= 1) {
        a += __shfl_xor_sync(0xffffffffu, a, o);
        bsum += __shfl_xor_sync(0xffffffffu, bsum, o);
    }
    float mu2 = a * (1.f / DD);
    float var2 = bsum * (1.f / DD) - mu2 * mu2;
    float rstd2 = rsqrtf(var2 + 1e-5f);
#pragma unroll
    for (int e = 0; e < 16; ++e) {
        int c = e * 32 + lane;
        orow[c] = (v[e] - mu2) * rstd2 * gact[c] + bact[c];
    }
}

// ---------- weight update: out = l2norm_rows(W*(1-decay_i) + alpha_j*(G@W)), both mats ----------
#define RPC 8
__global__ __launch_bounds__(512) void weight_update(const float* __restrict__ W0,
                                                     const float* __restrict__ G0,
                                                     const float* __restrict__ W1,
                                                     const float* __restrict__ G1,
                                                     const float* __restrict__ alpha,
                                                     const float* __restrict__ decay,
                                                     float* __restrict__ out0,
                                                     float* __restrict__ out1) {
    const float* Wm = blockIdx.y ? W1 : W0;
    const float* G = blockIdx.y ? G1 : G0;
    float* outp = blockIdx.y ? out1 : out0;

    const int i0 = blockIdx.x * RPC;
    const int j = threadIdx.x;
    const int lane = j & 31;
    const int w = j >> 5;

    __shared__ float Gsm[RPC][DD];
    __shared__ float red[16];
    __shared__ float norms[RPC];

#pragma unroll
    for (int r = 0; r < RPC; ++r) Gsm[r][j] = G[(size_t)(i0 + r) * DD + j];
    __syncthreads();

    float acc[RPC];
#pragma unroll
    for (int r = 0; r < RPC; ++r) acc[r] = 0.f;

#pragma unroll 4
    for (int k = 0; k < DD; ++k) {
        float wv = Wm[(size_t)k * DD + j];
#pragma unroll
        for (int r = 0; r < RPC; ++r) acc[r] = fmaf(Gsm[r][k], wv, acc[r]);
    }

    float aj = alpha[j];
#pragma unroll
    for (int r = 0; r < RPC; ++r)
        acc[r] = Wm[(size_t)(i0 + r) * DD + j] * (1.f - decay[i0 + r]) + aj * acc[r];

    for (int r = 0; r < RPC; ++r) {
        float s = acc[r] * acc[r];
#pragma unroll
        for (int o = 16; o; o >>= 1) s += __shfl_xor_sync(0xffffffffu, s, o);
        if (lane == 0) red[w] = s;
        __syncthreads();
        if (j == 0) {
            float tsum = 0.f;
#pragma unroll
            for (int q = 0; q < 16; ++q) tsum += red[q];
            norms[r] = fmaxf(sqrtf(tsum), 1e-12f);
        }
        __syncthreads();
    }

#pragma unroll
    for (int r = 0; r < RPC; ++r)
        outp[(size_t)(i0 + r) * DD + j] = acc[r] / norms[r];
}

// ---------------- launch ----------------
extern "C" void kernel_launch(void* const* d_in, const int* in_sizes, int n_in,
                              void* d_out, int out_size) {
    const float* stim = (const float*)d_in[0];
    const float* prev = (const float*)d_in[1];
    const float* W    = (const float*)d_in[2];
    const float* Wr   = (const float*)d_in[3];
    const float* alpha = (const float*)d_in[4];
    const float* decay = (const float*)d_in[5];
    const float* gact = (const float*)d_in[6];
    const float* bact = (const float*)d_in[7];
    const float* grec = (const float*)d_in[8];
    const float* brec = (const float*)d_in[9];
    float* out = (float*)d_out;

    const long Brows = in_sizes[0] / DD;  // 32768

    bf16 *s_hi, *s_lo, *p_hi, *p_lo, *st_hi, *st_lo, *pt_hi, *pt_lo;
    bf16 *wt_hi, *wt_lo, *wrt_hi, *wrt_lo;
    float *stim_out, *rec_out, *partS, *partP, *GS, *GP;
    cudaGetSymbolAddress((void**)&s_hi, g_s_hi);
    cudaGetSymbolAddress((void**)&s_lo, g_s_lo);
    cudaGetSymbolAddress((void**)&p_hi, g_p_hi);
    cudaGetSymbolAddress((void**)&p_lo, g_p_lo);
    cudaGetSymbolAddress((void**)&st_hi, g_st_hi);
    cudaGetSymbolAddress((void**)&st_lo, g_st_lo);
    cudaGetSymbolAddress((void**)&pt_hi, g_pt_hi);
    cudaGetSymbolAddress((void**)&pt_lo, g_pt_lo);
    cudaGetSymbolAddress((void**)&wt_hi, g_wt_hi);
    cudaGetSymbolAddress((void**)&wt_lo, g_wt_lo);
    cudaGetSymbolAddress((void**)&wrt_hi, g_wrt_hi);
    cudaGetSymbolAddress((void**)&wrt_lo, g_wrt_lo);
    cudaGetSymbolAddress((void**)&stim_out, g_stim_out);
    cudaGetSymbolAddress((void**)&rec_out, g_rec_out);
    cudaGetSymbolAddress((void**)&partS, g_partS);
    cudaGetSymbolAddress((void**)&partP, g_partP);
    cudaGetSymbolAddress((void**)&GS, g_GS);
    cudaGetSymbolAddress((void**)&GP, g_GP);

    cudaFuncSetAttribute(mma_all, cudaFuncAttributeMaxDynamicSharedMemorySize, SMEM_DYN);

    // launches 0-2: prep (mma_all stays at ncu capture index 3)
    dim3 tb(32, 8);
    split_both<<<dim3(DD / 32, Brows / 32), tb>>>(stim, s_hi, s_lo, st_hi, st_lo, Brows, DD);
    split_both<<<dim3(DD / 32, Brows / 32), tb>>>(prev, p_hi, p_lo, pt_hi, pt_lo, Brows, DD);
    split_w2<<<dim3(DD / 32, DD / 32, 2), tb>>>(W, Wr, wt_hi, wt_lo, wrt_hi, wrt_lo);

    // launch 3: ALL four GEMMs merged, gram blocks first (LPT order)
    const int fwdBlocks = (int)(Brows / MT) * (DD / NT);  // 256*8 = 2048
    const int gramBlocks = 20 * NSPLIT;                   // 320
    const int kcg = (int)(Brows / NSPLIT);                // 2048
    Seg4 segs;
    segs.s[0] = {st_hi, st_lo, st_hi, st_lo, Brows, Brows, partS, (long)DD * DD, kcg, 1, 0};
    segs.s[1] = {pt_hi, pt_lo, pt_hi, pt_lo, Brows, Brows, partP, (long)DD * DD, kcg, 1, gramBlocks};
    segs.s[2] = {s_hi, s_lo, wt_hi, wt_lo, DD, DD, stim_out, 0, DD, 0, 2 * gramBlocks};
    segs.s[3] = {p_hi, p_lo, wrt_hi, wrt_lo, DD, DD, rec_out, 0, DD, 0, 2 * gramBlocks + fwdBlocks};
    mma_all<<<2 * gramBlocks + 2 * fwdBlocks, 256, SMEM_DYN>>>(segs);

    reduce_gram<<<(DD * DD) / 256, 256>>>();

    ln_fuse<<<(unsigned)(Brows / 8), 256>>>(rec_out, stim_out, grec, brec, gact, bact, out);

    size_t off = (size_t)Brows * DD;
    weight_update<<<dim3(DD / RPC, 2), 512>>>(W, GS, Wr, GP, alpha, decay,
                                              out + off, out + off + (size_t)DD * DD);
}